// round 11
// baseline (speedup 1.0000x reference)
#include <cuda_runtime.h>
#include <math.h>

// ---------------- problem constants ----------------
constexpr int BATCH = 2, HH = 128, WW = 128, CH = 256;
constexpr int HEADS = 8, HD = 32;
constexpr int NPIX = BATCH * HH * WW;   // 32768
constexpr int C3 = 3 * CH;              // 768
constexpr int NREL = 23 * 23;           // 529

// ---------------- device scratch (allocation-free) ----------------
__device__ float g_qkv[NPIX * C3];
__device__ float g_qn [NPIX * CH];
__device__ float g_kn [NPIX * CH];
__device__ float g_v  [NPIX * CH];
__device__ float g_att[NPIX * CH];
__device__ float g_btab[NREL * HEADS];

// ---------------- CPB relative-bias MLP ----------------
__device__ __forceinline__ float relcoord(int r) {
    float cs = (float)(r - 11) * (8.0f / 7.0f);
    float a = log1pf(fabsf(cs)) * (1.0f / 2.0794415416798357f);
    return cs > 0.0f ? a : (cs < 0.0f ? -a : 0.0f);
}

__global__ void cpb_kernel(const float* __restrict__ w1, const float* __restrict__ b1,
                           const float* __restrict__ w2, float* __restrict__ btab) {
    int i = blockIdx.x;
    float y0 = relcoord(i / 23), y1 = relcoord(i % 23);
    int t = threadIdx.x;
    float part[HEADS];
#pragma unroll
    for (int hh = 0; hh < HEADS; hh++) part[hh] = 0.0f;
    for (int j = t; j < 512; j += 256) {
        float hv = fmaf(y0, w1[j], fmaf(y1, w1[512 + j], b1[j]));
        hv = fmaxf(hv, 0.0f);
#pragma unroll
        for (int hh = 0; hh < HEADS; hh++) part[hh] = fmaf(hv, w2[j * HEADS + hh], part[hh]);
    }
#pragma unroll
    for (int hh = 0; hh < HEADS; hh++)
#pragma unroll
        for (int o = 16; o; o >>= 1) part[hh] += __shfl_xor_sync(0xffffffffu, part[hh], o);
    __shared__ float sm[HEADS][8];
    int lane = t & 31, wrp = t >> 5;
    if (lane == 0)
        for (int hh = 0; hh < HEADS; hh++) sm[hh][wrp] = part[hh];
    __syncthreads();
    if (t < HEADS) {
        float ssum = 0.0f;
        for (int k = 0; k < 8; k++) ssum += sm[t][k];
        btab[i * HEADS + t] = 16.0f / (1.0f + expf(-ssum));
    }
}

// ---------------- tf32 helpers ----------------
__device__ __forceinline__ unsigned f2tf32(float x) {
    unsigned r;
    asm("cvt.rna.tf32.f32 %0, %1;" : "=r"(r) : "f"(x));
    return r;
}
__device__ __forceinline__ void split_tf32(float x, unsigned& hi, unsigned& lo) {
    hi = f2tf32(x);
    lo = f2tf32(x - __uint_as_float(hi));
}
#define MMA_TF32(C, A0, A1, A2, A3, B0, B1)                                    \
    asm volatile(                                                              \
        "mma.sync.aligned.m16n8k8.row.col.f32.tf32.tf32.f32 "                  \
        "{%0,%1,%2,%3}, {%4,%5,%6,%7}, {%8,%9}, {%0,%1,%2,%3};"                \
        : "+f"((C)[0]), "+f"((C)[1]), "+f"((C)[2]), "+f"((C)[3])               \
        : "r"(A0), "r"(A1), "r"(A2), "r"(A3), "r"(B0), "r"(B1))

// ---------------- tf32 tensor-core GEMM, BK=16 double-buffered, 2 blocks/SM, K=256 ----------------
constexpr int GBM = 128, GBN = 128, GBK = 16, GK = 256;
constexpr int AST = GBK + 4;   // 20
constexpr int BST = GBN + 8;   // 136
constexpr int ABUF = GBM * AST;
constexpr int BBUF = GBK * BST;
constexpr int GEMM_SMEM = 2 * (ABUF + BBUF) * 4;  // 37888 bytes

__global__ __launch_bounds__(256, 2) void mma_gemm(int M, int N,
                                                   const float* __restrict__ A,
                                                   const float* __restrict__ B,
                                                   float* __restrict__ C) {
    extern __shared__ unsigned smu[];
    unsigned* Asb[2] = {smu, smu + ABUF};
    unsigned* Bsb[2] = {smu + 2 * ABUF, smu + 2 * ABUF + BBUF};

    int tid = threadIdx.x;
    int warp = tid >> 5, lane = tid & 31;
    int wm = (warp & 1) * 64, wn = (warp >> 1) * 32;
    int brow = blockIdx.y * GBM, bcol = blockIdx.x * GBN;
    int grp = lane >> 2, thr = lane & 3;

    float acc[4][4][4];
#pragma unroll
    for (int i = 0; i < 4; i++)
#pragma unroll
        for (int j = 0; j < 4; j++)
#pragma unroll
            for (int r = 0; r < 4; r++) acc[i][j][r] = 0.0f;

    int aRow = tid >> 1, aCol = (tid & 1) << 3;
    int bRow = tid >> 4, bCol = (tid & 15) << 3;

    const float* Ap = A + (size_t)(brow + aRow) * GK + aCol;
    const float* Bp = B + (size_t)bRow * N + bcol + bCol;

    float4 ra[2], rb[2];
    constexpr int niter = GK / GBK;   // 16

#pragma unroll
    for (int i = 0; i < 2; i++) ra[i] = *(const float4*)(Ap + i * 4);
#pragma unroll
    for (int i = 0; i < 2; i++) rb[i] = *(const float4*)(Bp + i * 4);
#pragma unroll
    for (int i = 0; i < 2; i++) {
        unsigned* d = &Asb[0][aRow * AST + aCol + i * 4];
        d[0] = f2tf32(ra[i].x); d[1] = f2tf32(ra[i].y);
        d[2] = f2tf32(ra[i].z); d[3] = f2tf32(ra[i].w);
        unsigned* e = &Bsb[0][bRow * BST + bCol + i * 4];
        e[0] = f2tf32(rb[i].x); e[1] = f2tf32(rb[i].y);
        e[2] = f2tf32(rb[i].z); e[3] = f2tf32(rb[i].w);
    }
    __syncthreads();

    for (int iter = 0; iter < niter; iter++) {
        int nxt = iter + 1;
        if (nxt < niter) {
#pragma unroll
            for (int i = 0; i < 2; i++) ra[i] = *(const float4*)(Ap + nxt * GBK + i * 4);
#pragma unroll
            for (int i = 0; i < 2; i++) rb[i] = *(const float4*)(Bp + (size_t)nxt * GBK * N + i * 4);
        }
        const unsigned* Acur = Asb[iter & 1];
        const unsigned* Bcur = Bsb[iter & 1];
#pragma unroll
        for (int kstep = 0; kstep < 2; kstep++) {
            int kb = kstep * 8;
            unsigned a[4][4], bfr[4][2];
#pragma unroll
            for (int mt = 0; mt < 4; mt++) {
                int r0 = wm + mt * 16 + grp;
                int ca = kb + thr;
                a[mt][0] = Acur[r0 * AST + ca];
                a[mt][1] = Acur[(r0 + 8) * AST + ca];
                a[mt][2] = Acur[r0 * AST + ca + 4];
                a[mt][3] = Acur[(r0 + 8) * AST + ca + 4];
            }
#pragma unroll
            for (int nt = 0; nt < 4; nt++) {
                int kr = kb + thr;
                int nc = wn + nt * 8 + grp;
                bfr[nt][0] = Bcur[kr * BST + nc];
                bfr[nt][1] = Bcur[(kr + 4) * BST + nc];
            }
#pragma unroll
            for (int mt = 0; mt < 4; mt++)
#pragma unroll
                for (int nt = 0; nt < 4; nt++)
                    MMA_TF32(acc[mt][nt], a[mt][0], a[mt][1], a[mt][2], a[mt][3],
                             bfr[nt][0], bfr[nt][1]);
        }
        if (nxt < niter) {
            unsigned* Anx = Asb[nxt & 1];
            unsigned* Bnx = Bsb[nxt & 1];
#pragma unroll
            for (int i = 0; i < 2; i++) {
                unsigned* d = &Anx[aRow * AST + aCol + i * 4];
                d[0] = f2tf32(ra[i].x); d[1] = f2tf32(ra[i].y);
                d[2] = f2tf32(ra[i].z); d[3] = f2tf32(ra[i].w);
                unsigned* e = &Bnx[bRow * BST + bCol + i * 4];
                e[0] = f2tf32(rb[i].x); e[1] = f2tf32(rb[i].y);
                e[2] = f2tf32(rb[i].z); e[3] = f2tf32(rb[i].w);
            }
            __syncthreads();
        }
    }

#pragma unroll
    for (int mt = 0; mt < 4; mt++) {
#pragma unroll
        for (int nt = 0; nt < 4; nt++) {
            int row = brow + wm + mt * 16 + grp;
            int col = bcol + wn + nt * 8 + thr * 2;
            float2 v0 = {acc[mt][nt][0], acc[mt][nt][1]};
            float2 v1 = {acc[mt][nt][2], acc[mt][nt][3]};
            *(float2*)(C + (size_t)row * N + col) = v0;
            *(float2*)(C + (size_t)(row + 8) * N + col) = v1;
        }
    }
}

// ---------------- conv + LN + biases + l2norm: 2x4 pixel tile / block, 192 threads ----------------
// patch = 4 rows x 6 cols float4 -> 3.0 loads/pixel; per-channel fmaf order unchanged.
__global__ __launch_bounds__(192) void conv_ln_kernel(
    const float* __restrict__ qkv, const float* __restrict__ wdw,
    const float* __restrict__ ln_g, const float* __restrict__ ln_b,
    const float* __restrict__ q_bias, const float* __restrict__ v_bias,
    const float* __restrict__ logit_scale,
    float* __restrict__ qn, float* __restrict__ kn, float* __restrict__ vv) {
    int bid = blockIdx.x;                  // 4096 blocks: 2 batch x 64 row-pairs x 32 col-quads
    int b = bid >> 11;
    int rem = bid & 2047;
    int y0 = (rem >> 5) << 1;              // 0,2,..,126
    int x0 = (rem & 31) << 2;              // 0,4,..,124
    int t = threadIdx.x;                   // channels 4t..4t+3
    int c = t << 2;

    float4 wv[9];
#pragma unroll
    for (int i = 0; i < 9; i++) wv[i] = *(const float4*)&wdw[i * C3 + c];

    float4 cv[8];                          // [row 0..1][col 0..3] => p = prow*4 + pcol
#pragma unroll
    for (int p = 0; p < 8; p++) cv[p] = make_float4(0.f, 0.f, 0.f, 0.f);

    // stream 4 patch rows; each applied to the output rows it covers
#pragma unroll
    for (int pr = 0; pr < 4; pr++) {
        int yy = y0 + pr - 1;
        if ((unsigned)yy >= (unsigned)HH) continue;
        float4 rv[6];
#pragma unroll
        for (int dx = 0; dx < 6; dx++) {
            int xx = x0 + dx - 1;
            if ((unsigned)xx < (unsigned)WW)
                rv[dx] = *(const float4*)&qkv[(size_t)(((b << 7) | yy) << 7 | xx) * C3 + c];
            else
                rv[dx] = make_float4(0.f, 0.f, 0.f, 0.f);
        }
#pragma unroll
        for (int r_out = 0; r_out < 2; r_out++) {
            int ky = pr - r_out;
            if (ky < 0 || ky > 2) continue;
#pragma unroll
            for (int pcol = 0; pcol < 4; pcol++) {
#pragma unroll
                for (int kx = 0; kx < 3; kx++) {
                    float4 wk = wv[ky * 3 + kx];
                    float4 xv = rv[pcol + kx];
                    float4& a = cv[r_out * 4 + pcol];
                    a.x = fmaf(wk.x, xv.x, a.x);
                    a.y = fmaf(wk.y, xv.y, a.y);
                    a.z = fmaf(wk.z, xv.z, a.z);
                    a.w = fmaf(wk.w, xv.w, a.w);
                }
            }
        }
    }

    // global pixel indices for the 8 outputs
    int pidx[8];
#pragma unroll
    for (int p = 0; p < 8; p++) {
        int prow = p >> 2, pcol = p & 3;
        pidx[p] = (((b << 7) | (y0 + prow)) << 7) | (x0 + pcol);
    }

    // LN reductions, 8 pixels at once
    float s[8], s2[8];
#pragma unroll
    for (int p = 0; p < 8; p++) {
        s[p]  = cv[p].x + cv[p].y + cv[p].z + cv[p].w;
        s2[p] = cv[p].x * cv[p].x + cv[p].y * cv[p].y + cv[p].z * cv[p].z + cv[p].w * cv[p].w;
    }
#pragma unroll
    for (int o = 16; o; o >>= 1) {
#pragma unroll
        for (int p = 0; p < 8; p++) {
            s[p]  += __shfl_xor_sync(0xffffffffu, s[p], o);
            s2[p] += __shfl_xor_sync(0xffffffffu, s2[p], o);
        }
    }
    __shared__ float ws[6][8], ws2[6][8];
    __shared__ float s_mu[8], s_rstd[8];
    int lane = t & 31, wrp = t >> 5;
    if (lane == 0) {
#pragma unroll
        for (int p = 0; p < 8; p++) { ws[wrp][p] = s[p]; ws2[wrp][p] = s2[p]; }
    }
    __syncthreads();
    if (t < 64) {
        int p = t >> 3, j = t & 7;
        float a1 = (j < 6) ? ws[j][p]  : 0.0f;
        float a2 = (j < 6) ? ws2[j][p] : 0.0f;
#pragma unroll
        for (int o = 4; o; o >>= 1) {
            a1 += __shfl_xor_sync(0xffffffffu, a1, o);
            a2 += __shfl_xor_sync(0xffffffffu, a2, o);
        }
        if (j == 0) {
            float mu = a1 * (1.0f / 768.0f);
            float var = a2 * (1.0f / 768.0f) - mu * mu;
            s_mu[p] = mu;
            s_rstd[p] = rsqrtf(var + 1e-5f);
        }
    }
    __syncthreads();

    float4 g  = *(const float4*)&ln_g[c];
    float4 bb = *(const float4*)&ln_b[c];
    float4 vn[8];
#pragma unroll
    for (int p = 0; p < 8; p++) {
        float mu = s_mu[p], rstd = s_rstd[p];
        vn[p].x = (cv[p].x - mu) * rstd * g.x + bb.x;
        vn[p].y = (cv[p].y - mu) * rstd * g.y + bb.y;
        vn[p].z = (cv[p].z - mu) * rstd * g.z + bb.z;
        vn[p].w = (cv[p].w - mu) * rstd * g.w + bb.w;
    }

    if (t < 64) {
        float4 qb = *(const float4*)&q_bias[c];
        float sc = __expf(fminf(logit_scale[t >> 3], 4.6051701859880914f));
        float ss[8];
#pragma unroll
        for (int p = 0; p < 8; p++) {
            vn[p].x += qb.x; vn[p].y += qb.y; vn[p].z += qb.z; vn[p].w += qb.w;
            ss[p] = vn[p].x * vn[p].x + vn[p].y * vn[p].y +
                    vn[p].z * vn[p].z + vn[p].w * vn[p].w;
        }
#pragma unroll
        for (int o = 4; o; o >>= 1)
#pragma unroll
            for (int p = 0; p < 8; p++) ss[p] += __shfl_xor_sync(0xffffffffu, ss[p], o);
#pragma unroll
        for (int p = 0; p < 8; p++) {
            float rn = rsqrtf(fmaxf(ss[p], 1.55e-5f)) * sc;
            float4 o4 = {vn[p].x * rn, vn[p].y * rn, vn[p].z * rn, vn[p].w * rn};
            *(float4*)&qn[(size_t)pidx[p] * CH + c] = o4;
        }
    } else if (t < 128) {
        int cc = c - 256;
        float ss[8];
#pragma unroll
        for (int p = 0; p < 8; p++)
            ss[p] = vn[p].x * vn[p].x + vn[p].y * vn[p].y +
                    vn[p].z * vn[p].z + vn[p].w * vn[p].w;
#pragma unroll
        for (int o = 4; o; o >>= 1)
#pragma unroll
            for (int p = 0; p < 8; p++) ss[p] += __shfl_xor_sync(0xffffffffu, ss[p], o);
#pragma unroll
        for (int p = 0; p < 8; p++) {
            float rn = rsqrtf(fmaxf(ss[p], 1.55e-5f));
            float4 o4 = {vn[p].x * rn, vn[p].y * rn, vn[p].z * rn, vn[p].w * rn};
            *(float4*)&kn[(size_t)pidx[p] * CH + cc] = o4;
        }
    } else {
        int cc = c - 512;
        float4 vb = *(const float4*)&v_bias[cc];
#pragma unroll
        for (int p = 0; p < 8; p++) {
            float4 o4 = {vn[p].x + vb.x, vn[p].y + vb.y, vn[p].z + vb.z, vn[p].w + vb.w};
            *(float4*)&vv[(size_t)pidx[p] * CH + cc] = o4;
        }
    }
}

// ---------------- attention: split-tf32 QK^T, single-tf32 PV (unchanged R8) ----------------
constexpr int A_QSH = 0;
constexpr int A_QSL = A_QSH + 64 * 36;
constexpr int A_KSH = A_QSL + 64 * 36;
constexpr int A_KSL = A_KSH + 32 * 72;
constexpr int A_VS  = A_KSL + 32 * 72;
constexpr int A_SP  = A_VS + 64 * 40;
constexpr int A_BSM = A_SP + 64 * 68;
constexpr int A_LRD = A_BSM + NREL;
constexpr int A_LFN = A_LRD + 256;
constexpr int A_TOT = A_LFN + 64;

__global__ __launch_bounds__(256, 2) void attn_kernel(
    const float* __restrict__ qn, const float* __restrict__ kn,
    const float* __restrict__ vv, const float* __restrict__ btab,
    const float* __restrict__ logit_scale, float* __restrict__ out) {
    extern __shared__ float sm[];
    float* QsH = sm + A_QSH;  float* QsL = sm + A_QSL;
    float* KsH = sm + A_KSH;  float* KsL = sm + A_KSL;
    float* Vs  = sm + A_VS;
    float* Sp  = sm + A_SP;
    float* bsm = sm + A_BSM;
    float* lrd = sm + A_LRD;
    float* lfn = sm + A_LFN;

    int w = blockIdx.x, h = blockIdx.y;
    int b = w >> 8, wr = (w >> 4) & 15, wc = w & 15;
    int t = threadIdx.x;
    int warp = t >> 5, lane = t & 31, grp = lane >> 2, thr = lane & 3;
    float bound = __expf(fminf(logit_scale[h], 4.6051701859880914f)) + 16.0f;

    for (int i = t; i < NREL; i += 256) bsm[i] = btab[i * HEADS + h];

    {
        int row = t & 63, d0 = (t >> 6) << 3;
        int py = wr * 8 + (row >> 3), px = wc * 8 + (row & 7);
        const float* qp = qn + (size_t)(((b << 7) | py) << 7 | px) * CH + h * HD + d0;
        float4 a = *(const float4*)qp;
        float4 bq = *(const float4*)(qp + 4);
        float v[8] = {a.x, a.y, a.z, a.w, bq.x, bq.y, bq.z, bq.w};
#pragma unroll
        for (int i = 0; i < 8; i++) {
            unsigned hb, lb;
            split_tf32(v[i], hb, lb);
            QsH[row * 36 + d0 + i] = __uint_as_float(hb);
            QsL[row * 36 + d0 + i] = __uint_as_float(lb);
        }
    }

    int wmA = (warp & 1) * 32, wnA = (warp >> 1) * 16;
    int mB = warp & 3, nB = warp >> 2;

    float oacc[2][4];
#pragma unroll
    for (int nt = 0; nt < 2; nt++)
#pragma unroll
        for (int r = 0; r < 4; r++) oacc[nt][r] = 0.0f;
    float rs[4] = {0.0f, 0.0f, 0.0f, 0.0f};

    for (int c0 = 0; c0 < 4; c0++) {
        __syncthreads();
        {
            int j = t & 63, d1 = (t >> 6) << 3;
            int jg = (c0 << 6) + j;
            int kr = jg >> 4, kc = jg & 15;
            int gy = wr * 8 - 4 + kr, gx = wc * 8 - 4 + kc;
            float kv[8] = {0, 0, 0, 0, 0, 0, 0, 0};
            float vvv[8] = {0, 0, 0, 0, 0, 0, 0, 0};
            if ((unsigned)gy < 128u && (unsigned)gx < 128u) {
                size_t gb = (size_t)(((b << 7) | gy) << 7 | gx) * CH + h * HD + d1;
                float4 k0 = *(const float4*)(kn + gb), k1 = *(const float4*)(kn + gb + 4);
                float4 v0 = *(const float4*)(vv + gb), v1 = *(const float4*)(vv + gb + 4);
                kv[0] = k0.x; kv[1] = k0.y; kv[2] = k0.z; kv[3] = k0.w;
                kv[4] = k1.x; kv[5] = k1.y; kv[6] = k1.z; kv[7] = k1.w;
                vvv[0] = v0.x; vvv[1] = v0.y; vvv[2] = v0.z; vvv[3] = v0.w;
                vvv[4] = v1.x; vvv[5] = v1.y; vvv[6] = v1.z; vvv[7] = v1.w;
            }
#pragma unroll
            for (int i = 0; i < 8; i++) {
                unsigned hb, lb;
                split_tf32(kv[i], hb, lb);
                KsH[(d1 + i) * 72 + j] = __uint_as_float(hb);
                KsL[(d1 + i) * 72 + j] = __uint_as_float(lb);
            }
            float vh[8];
#pragma unroll
            for (int i = 0; i < 8; i++) vh[i] = __uint_as_float(f2tf32(vvv[i]));
            *(float4*)&Vs[j * 40 + d1]     = *(float4*)&vh[0];
            *(float4*)&Vs[j * 40 + d1 + 4] = *(float4*)&vh[4];
        }
        __syncthreads();

        float acc[2][2][4];
#pragma unroll
        for (int mt = 0; mt < 2; mt++)
#pragma unroll
            for (int nt = 0; nt < 2; nt++)
#pragma unroll
                for (int r = 0; r < 4; r++) acc[mt][nt][r] = 0.0f;

        const unsigned* QH = (const unsigned*)QsH;
        const unsigned* QL = (const unsigned*)QsL;
        const unsigned* KH = (const unsigned*)KsH;
        const unsigned* KL = (const unsigned*)KsL;
#pragma unroll
        for (int ks = 0; ks < 4; ks++) {
            int kb = ks * 8;
            unsigned aH[2][4], aL[2][4], bH[2][2], bL[2][2];
#pragma unroll
            for (int mt = 0; mt < 2; mt++) {
                int r0 = wmA + mt * 16 + grp;
                int ca = kb + thr;
                aH[mt][0] = QH[r0 * 36 + ca];       aH[mt][1] = QH[(r0 + 8) * 36 + ca];
                aH[mt][2] = QH[r0 * 36 + ca + 4];   aH[mt][3] = QH[(r0 + 8) * 36 + ca + 4];
                aL[mt][0] = QL[r0 * 36 + ca];       aL[mt][1] = QL[(r0 + 8) * 36 + ca];
                aL[mt][2] = QL[r0 * 36 + ca + 4];   aL[mt][3] = QL[(r0 + 8) * 36 + ca + 4];
            }
#pragma unroll
            for (int nt = 0; nt < 2; nt++) {
                int nc = wnA + nt * 8 + grp;
                bH[nt][0] = KH[(kb + thr) * 72 + nc];
                bH[nt][1] = KH[(kb + thr + 4) * 72 + nc];
                bL[nt][0] = KL[(kb + thr) * 72 + nc];
                bL[nt][1] = KL[(kb + thr + 4) * 72 + nc];
            }
#pragma unroll
            for (int mt = 0; mt < 2; mt++)
#pragma unroll
                for (int nt = 0; nt < 2; nt++) {
                    MMA_TF32(acc[mt][nt], aH[mt][0], aH[mt][1], aH[mt][2], aH[mt][3],
                             bH[nt][0], bH[nt][1]);
                    MMA_TF32(acc[mt][nt], aH[mt][0], aH[mt][1], aH[mt][2], aH[mt][3],
                             bL[nt][0], bL[nt][1]);
                    MMA_TF32(acc[mt][nt], aL[mt][0], aL[mt][1], aL[mt][2], aL[mt][3],
                             bH[nt][0], bH[nt][1]);
                }
        }

        int cbg = c0 << 6;
#pragma unroll
        for (int mt = 0; mt < 2; mt++) {
            int r0 = wmA + mt * 16 + grp, r1 = r0 + 8;
            int q0 = (r0 >> 3) * 23 + (r0 & 7);
            int q1 = (r1 >> 3) * 23 + (r1 & 7);
#pragma unroll
            for (int nt = 0; nt < 2; nt++) {
                int lc = wnA + nt * 8 + 2 * thr;
                int jg0 = cbg + lc, jg1 = jg0 + 1;
                int b0 = (15 - (jg0 >> 4)) * 23 + (15 - (jg0 & 15));
                int b1 = (15 - (jg1 >> 4)) * 23 + (15 - (jg1 & 15));
                float p00 = __expf(acc[mt][nt][0] - bound + bsm[b0 + q0]);
                float p01 = __expf(acc[mt][nt][1] - bound + bsm[b1 + q0]);
                float p10 = __expf(acc[mt][nt][2] - bound + bsm[b0 + q1]);
                float p11 = __expf(acc[mt][nt][3] - bound + bsm[b1 + q1]);
                rs[mt * 2]     += p00 + p01;
                rs[mt * 2 + 1] += p10 + p11;
                float2 w0 = {__uint_as_float(f2tf32(p00)), __uint_as_float(f2tf32(p01))};
                float2 w1 = {__uint_as_float(f2tf32(p10)), __uint_as_float(f2tf32(p11))};
                *(float2*)&Sp[r0 * 68 + lc] = w0;
                *(float2*)&Sp[r1 * 68 + lc] = w1;
            }
        }
        __syncthreads();

        const unsigned* SPu = (const unsigned*)Sp;
        const unsigned* VU  = (const unsigned*)Vs;
        int ra = mB * 16 + grp;
#pragma unroll
        for (int ks = 0; ks < 8; ks++) {
            int kb = ks * 8;
            unsigned a0 = SPu[ra * 68 + kb + thr];
            unsigned a1 = SPu[(ra + 8) * 68 + kb + thr];
            unsigned a2 = SPu[ra * 68 + kb + thr + 4];
            unsigned a3 = SPu[(ra + 8) * 68 + kb + thr + 4];
#pragma unroll
            for (int nt = 0; nt < 2; nt++) {
                int col = nB * 16 + nt * 8 + grp;
                unsigned b0 = VU[(kb + thr) * 40 + col];
                unsigned b1 = VU[(kb + thr + 4) * 40 + col];
                MMA_TF32(oacc[nt], a0, a1, a2, a3, b0, b1);
            }
        }
    }

#pragma unroll
    for (int i = 0; i < 4; i++) {
        rs[i] += __shfl_xor_sync(0xffffffffu, rs[i], 1);
        rs[i] += __shfl_xor_sync(0xffffffffu, rs[i], 2);
    }
    if (thr == 0) {
#pragma unroll
        for (int mt = 0; mt < 2; mt++) {
#pragma unroll
            for (int hh = 0; hh < 2; hh++) {
                int row = wmA + mt * 16 + hh * 8 + grp;
                lrd[(warp >> 1) * 64 + row] = rs[mt * 2 + hh];
            }
        }
    }
    __syncthreads();
    if (t < 64)
        lfn[t] = 1.0f / (lrd[t] + lrd[64 + t] + lrd[128 + t] + lrd[192 + t]);
    __syncthreads();

    {
        int r0 = mB * 16 + grp, r1 = r0 + 8;
        float inv0 = lfn[r0], inv1 = lfn[r1];
        int py0 = wr * 8 + (r0 >> 3), px0 = wc * 8 + (r0 & 7);
        int py1 = wr * 8 + (r1 >> 3), px1 = wc * 8 + (r1 & 7);
        float* op0 = out + (size_t)(((b << 7) | py0) << 7 | px0) * CH + h * HD;
        float* op1 = out + (size_t)(((b << 7) | py1) << 7 | px1) * CH + h * HD;
#pragma unroll
        for (int nt = 0; nt < 2; nt++) {
            int col = nB * 16 + nt * 8 + 2 * thr;
            float2 w0 = {oacc[nt][0] * inv0, oacc[nt][1] * inv0};
            float2 w1 = {oacc[nt][2] * inv1, oacc[nt][3] * inv1};
            *(float2*)(op0 + col) = w0;
            *(float2*)(op1 + col) = w1;
        }
    }
}

// ---------------- launch ----------------
extern "C" void kernel_launch(void* const* d_in, const int* in_sizes, int n_in,
                              void* d_out, int out_size) {
    const float* x           = (const float*)d_in[0];
    const float* w_qkv       = (const float*)d_in[1];
    const float* w_dw        = (const float*)d_in[2];
    const float* ln_g        = (const float*)d_in[3];
    const float* ln_b        = (const float*)d_in[4];
    const float* q_bias      = (const float*)d_in[5];
    const float* v_bias      = (const float*)d_in[6];
    const float* logit_scale = (const float*)d_in[7];
    const float* cpb_w1      = (const float*)d_in[8];
    const float* cpb_b1      = (const float*)d_in[9];
    const float* cpb_w2      = (const float*)d_in[10];
    const float* w_proj      = (const float*)d_in[11];
    float* out = (float*)d_out;

    float *qkv, *qn, *kn, *vv, *att, *btab;
    cudaGetSymbolAddress((void**)&qkv,  g_qkv);
    cudaGetSymbolAddress((void**)&qn,   g_qn);
    cudaGetSymbolAddress((void**)&kn,   g_kn);
    cudaGetSymbolAddress((void**)&vv,   g_v);
    cudaGetSymbolAddress((void**)&att,  g_att);
    cudaGetSymbolAddress((void**)&btab, g_btab);

    int smem_attn = A_TOT * 4;
    cudaFuncSetAttribute(attn_kernel, cudaFuncAttributeMaxDynamicSharedMemorySize, smem_attn);
    cudaFuncSetAttribute(mma_gemm, cudaFuncAttributeMaxDynamicSharedMemorySize, GEMM_SMEM);

    cpb_kernel<<<NREL, 256>>>(cpb_w1, cpb_b1, cpb_w2, btab);
    mma_gemm<<<dim3(C3 / 128, NPIX / 128), 256, GEMM_SMEM>>>(NPIX, C3, x, w_qkv, qkv);
    conv_ln_kernel<<<NPIX / 8, 192>>>(qkv, w_dw, ln_g, ln_b, q_bias, v_bias, logit_scale,
                                      qn, kn, vv);
    attn_kernel<<<dim3(512, 8), 256, smem_attn>>>(qn, kn, vv, btab, logit_scale, att);
    mma_gemm<<<dim3(CH / 128, NPIX / 128), 256, GEMM_SMEM>>>(NPIX, CH, att, w_proj, out);
}

// round 12
// speedup vs baseline: 1.0640x; 1.0640x over previous
#include <cuda_runtime.h>
#include <math.h>

// ---------------- problem constants ----------------
constexpr int BATCH = 2, HH = 128, WW = 128, CH = 256;
constexpr int HEADS = 8, HD = 32;
constexpr int NPIX = BATCH * HH * WW;   // 32768
constexpr int C3 = 3 * CH;              // 768
constexpr int NREL = 23 * 23;           // 529

// ---------------- device scratch (allocation-free) ----------------
__device__ float g_qkv[NPIX * C3];
__device__ float g_qn [NPIX * CH];
__device__ float g_kn [NPIX * CH];
__device__ float g_v  [NPIX * CH];
__device__ float g_att[NPIX * CH];
__device__ float g_btab[NREL * HEADS];

// ---------------- CPB relative-bias MLP ----------------
__device__ __forceinline__ float relcoord(int r) {
    float cs = (float)(r - 11) * (8.0f / 7.0f);
    float a = log1pf(fabsf(cs)) * (1.0f / 2.0794415416798357f);
    return cs > 0.0f ? a : (cs < 0.0f ? -a : 0.0f);
}

__global__ void cpb_kernel(const float* __restrict__ w1, const float* __restrict__ b1,
                           const float* __restrict__ w2, float* __restrict__ btab) {
    int i = blockIdx.x;
    float y0 = relcoord(i / 23), y1 = relcoord(i % 23);
    int t = threadIdx.x;
    float part[HEADS];
#pragma unroll
    for (int hh = 0; hh < HEADS; hh++) part[hh] = 0.0f;
    for (int j = t; j < 512; j += 256) {
        float hv = fmaf(y0, w1[j], fmaf(y1, w1[512 + j], b1[j]));
        hv = fmaxf(hv, 0.0f);
#pragma unroll
        for (int hh = 0; hh < HEADS; hh++) part[hh] = fmaf(hv, w2[j * HEADS + hh], part[hh]);
    }
#pragma unroll
    for (int hh = 0; hh < HEADS; hh++)
#pragma unroll
        for (int o = 16; o; o >>= 1) part[hh] += __shfl_xor_sync(0xffffffffu, part[hh], o);
    __shared__ float sm[HEADS][8];
    int lane = t & 31, wrp = t >> 5;
    if (lane == 0)
        for (int hh = 0; hh < HEADS; hh++) sm[hh][wrp] = part[hh];
    __syncthreads();
    if (t < HEADS) {
        float ssum = 0.0f;
        for (int k = 0; k < 8; k++) ssum += sm[t][k];
        btab[i * HEADS + t] = 16.0f / (1.0f + expf(-ssum));
    }
}

// ---------------- tf32 helpers ----------------
__device__ __forceinline__ unsigned f2tf32(float x) {
    unsigned r;
    asm("cvt.rna.tf32.f32 %0, %1;" : "=r"(r) : "f"(x));
    return r;
}
__device__ __forceinline__ void split_tf32(float x, unsigned& hi, unsigned& lo) {
    hi = f2tf32(x);
    lo = f2tf32(x - __uint_as_float(hi));
}
#define MMA_TF32(C, A0, A1, A2, A3, B0, B1)                                    \
    asm volatile(                                                              \
        "mma.sync.aligned.m16n8k8.row.col.f32.tf32.tf32.f32 "                  \
        "{%0,%1,%2,%3}, {%4,%5,%6,%7}, {%8,%9}, {%0,%1,%2,%3};"                \
        : "+f"((C)[0]), "+f"((C)[1]), "+f"((C)[2]), "+f"((C)[3])               \
        : "r"(A0), "r"(A1), "r"(A2), "r"(A3), "r"(B0), "r"(B1))

// ---------------- tf32 tensor-core GEMM, BK=16 double-buffered, 2 blocks/SM (R10) ----------------
constexpr int GBM = 128, GBN = 128, GBK = 16;
constexpr int AST = GBK + 4;   // 20
constexpr int BST = GBN + 8;   // 136
constexpr int ABUF = GBM * AST;
constexpr int BBUF = GBK * BST;
constexpr int GEMM_SMEM = 2 * (ABUF + BBUF) * 4;  // 37888 bytes

__global__ __launch_bounds__(256, 2) void mma_gemm(int M, int N, int K,
                                                   const float* __restrict__ A,
                                                   const float* __restrict__ B,
                                                   float* __restrict__ C) {
    extern __shared__ unsigned smu[];
    unsigned* Asb[2] = {smu, smu + ABUF};
    unsigned* Bsb[2] = {smu + 2 * ABUF, smu + 2 * ABUF + BBUF};

    int tid = threadIdx.x;
    int warp = tid >> 5, lane = tid & 31;
    int wm = (warp & 1) * 64, wn = (warp >> 1) * 32;
    int brow = blockIdx.y * GBM, bcol = blockIdx.x * GBN;
    int grp = lane >> 2, thr = lane & 3;

    float acc[4][4][4];
#pragma unroll
    for (int i = 0; i < 4; i++)
#pragma unroll
        for (int j = 0; j < 4; j++)
#pragma unroll
            for (int r = 0; r < 4; r++) acc[i][j][r] = 0.0f;

    int aRow = tid >> 1, aCol = (tid & 1) << 3;
    int bRow = tid >> 4, bCol = (tid & 15) << 3;

    const float* Ap = A + (size_t)(brow + aRow) * K + aCol;
    const float* Bp = B + (size_t)bRow * N + bcol + bCol;

    float4 ra[2], rb[2];
    int niter = K / GBK;

#pragma unroll
    for (int i = 0; i < 2; i++) ra[i] = *(const float4*)(Ap + i * 4);
#pragma unroll
    for (int i = 0; i < 2; i++) rb[i] = *(const float4*)(Bp + i * 4);
#pragma unroll
    for (int i = 0; i < 2; i++) {
        unsigned* d = &Asb[0][aRow * AST + aCol + i * 4];
        d[0] = f2tf32(ra[i].x); d[1] = f2tf32(ra[i].y);
        d[2] = f2tf32(ra[i].z); d[3] = f2tf32(ra[i].w);
        unsigned* e = &Bsb[0][bRow * BST + bCol + i * 4];
        e[0] = f2tf32(rb[i].x); e[1] = f2tf32(rb[i].y);
        e[2] = f2tf32(rb[i].z); e[3] = f2tf32(rb[i].w);
    }
    __syncthreads();

    for (int iter = 0; iter < niter; iter++) {
        int nxt = iter + 1;
        if (nxt < niter) {
#pragma unroll
            for (int i = 0; i < 2; i++) ra[i] = *(const float4*)(Ap + nxt * GBK + i * 4);
#pragma unroll
            for (int i = 0; i < 2; i++) rb[i] = *(const float4*)(Bp + (size_t)nxt * GBK * N + i * 4);
        }
        const unsigned* Acur = Asb[iter & 1];
        const unsigned* Bcur = Bsb[iter & 1];
#pragma unroll
        for (int kstep = 0; kstep < 2; kstep++) {
            int kb = kstep * 8;
            unsigned a[4][4], bfr[4][2];
#pragma unroll
            for (int mt = 0; mt < 4; mt++) {
                int r0 = wm + mt * 16 + grp;
                int ca = kb + thr;
                a[mt][0] = Acur[r0 * AST + ca];
                a[mt][1] = Acur[(r0 + 8) * AST + ca];
                a[mt][2] = Acur[r0 * AST + ca + 4];
                a[mt][3] = Acur[(r0 + 8) * AST + ca + 4];
            }
#pragma unroll
            for (int nt = 0; nt < 4; nt++) {
                int kr = kb + thr;
                int nc = wn + nt * 8 + grp;
                bfr[nt][0] = Bcur[kr * BST + nc];
                bfr[nt][1] = Bcur[(kr + 4) * BST + nc];
            }
#pragma unroll
            for (int mt = 0; mt < 4; mt++)
#pragma unroll
                for (int nt = 0; nt < 4; nt++)
                    MMA_TF32(acc[mt][nt], a[mt][0], a[mt][1], a[mt][2], a[mt][3],
                             bfr[nt][0], bfr[nt][1]);
        }
        if (nxt < niter) {
            unsigned* Anx = Asb[nxt & 1];
            unsigned* Bnx = Bsb[nxt & 1];
#pragma unroll
            for (int i = 0; i < 2; i++) {
                unsigned* d = &Anx[aRow * AST + aCol + i * 4];
                d[0] = f2tf32(ra[i].x); d[1] = f2tf32(ra[i].y);
                d[2] = f2tf32(ra[i].z); d[3] = f2tf32(ra[i].w);
                unsigned* e = &Bnx[bRow * BST + bCol + i * 4];
                e[0] = f2tf32(rb[i].x); e[1] = f2tf32(rb[i].y);
                e[2] = f2tf32(rb[i].z); e[3] = f2tf32(rb[i].w);
            }
            __syncthreads();
        }
    }

#pragma unroll
    for (int mt = 0; mt < 4; mt++) {
#pragma unroll
        for (int nt = 0; nt < 4; nt++) {
            int row = brow + wm + mt * 16 + grp;
            int col = bcol + wn + nt * 8 + thr * 2;
            float2 v0 = {acc[mt][nt][0], acc[mt][nt][1]};
            float2 v1 = {acc[mt][nt][2], acc[mt][nt][3]};
            *(float2*)(C + (size_t)row * N + col) = v0;
            *(float2*)(C + (size_t)(row + 8) * N + col) = v1;
        }
    }
}

// ---------------- conv + LN + biases + l2norm: 4 px/block, 192 threads (R10 exact) ----------------
__global__ __launch_bounds__(192) void conv_ln_kernel(
    const float* __restrict__ qkv, const float* __restrict__ wdw,
    const float* __restrict__ ln_g, const float* __restrict__ ln_b,
    const float* __restrict__ q_bias, const float* __restrict__ v_bias,
    const float* __restrict__ logit_scale,
    float* __restrict__ qn, float* __restrict__ kn, float* __restrict__ vv) {
    int pixbase = blockIdx.x << 2;
    int b = pixbase >> 14, y = (pixbase >> 7) & 127, x0 = pixbase & 127;
    int t = threadIdx.x;
    int c = t << 2;

    float4 wv[9];
#pragma unroll
    for (int i = 0; i < 9; i++) wv[i] = *(const float4*)&wdw[i * C3 + c];

    float4 cv[4];
#pragma unroll
    for (int p = 0; p < 4; p++) cv[p] = make_float4(0.f, 0.f, 0.f, 0.f);

#pragma unroll
    for (int dy = 0; dy < 3; dy++) {
        int yy = y + dy - 1;
        if ((unsigned)yy >= (unsigned)HH) continue;
        float4 rv[6];
#pragma unroll
        for (int dx = 0; dx < 6; dx++) {
            int xx = x0 + dx - 1;
            if ((unsigned)xx < (unsigned)WW)
                rv[dx] = *(const float4*)&qkv[(size_t)(((b << 7) | yy) << 7 | xx) * C3 + c];
            else
                rv[dx] = make_float4(0.f, 0.f, 0.f, 0.f);
        }
#pragma unroll
        for (int p = 0; p < 4; p++) {
#pragma unroll
            for (int kx = 0; kx < 3; kx++) {
                float4 wk = wv[dy * 3 + kx];
                float4 xv = rv[p + kx];
                cv[p].x = fmaf(wk.x, xv.x, cv[p].x);
                cv[p].y = fmaf(wk.y, xv.y, cv[p].y);
                cv[p].z = fmaf(wk.z, xv.z, cv[p].z);
                cv[p].w = fmaf(wk.w, xv.w, cv[p].w);
            }
        }
    }

    float s[4], s2[4];
#pragma unroll
    for (int p = 0; p < 4; p++) {
        s[p]  = cv[p].x + cv[p].y + cv[p].z + cv[p].w;
        s2[p] = cv[p].x * cv[p].x + cv[p].y * cv[p].y + cv[p].z * cv[p].z + cv[p].w * cv[p].w;
    }
#pragma unroll
    for (int o = 16; o; o >>= 1) {
#pragma unroll
        for (int p = 0; p < 4; p++) {
            s[p]  += __shfl_xor_sync(0xffffffffu, s[p], o);
            s2[p] += __shfl_xor_sync(0xffffffffu, s2[p], o);
        }
    }
    __shared__ float ws[6][4], ws2[6][4];
    __shared__ float s_mu[4], s_rstd[4];
    int lane = t & 31, wrp = t >> 5;
    if (lane == 0) {
#pragma unroll
        for (int p = 0; p < 4; p++) { ws[wrp][p] = s[p]; ws2[wrp][p] = s2[p]; }
    }
    __syncthreads();
    if (t < 32) {
        int p = t >> 3, j = t & 7;
        float a1 = (j < 6) ? ws[j][p]  : 0.0f;
        float a2 = (j < 6) ? ws2[j][p] : 0.0f;
#pragma unroll
        for (int o = 4; o; o >>= 1) {
            a1 += __shfl_xor_sync(0xffffffffu, a1, o);
            a2 += __shfl_xor_sync(0xffffffffu, a2, o);
        }
        if (j == 0) {
            float mu = a1 * (1.0f / 768.0f);
            float var = a2 * (1.0f / 768.0f) - mu * mu;
            s_mu[p] = mu;
            s_rstd[p] = rsqrtf(var + 1e-5f);
        }
    }
    __syncthreads();

    float4 g  = *(const float4*)&ln_g[c];
    float4 bb = *(const float4*)&ln_b[c];
    float4 vn[4];
#pragma unroll
    for (int p = 0; p < 4; p++) {
        float mu = s_mu[p], rstd = s_rstd[p];
        vn[p].x = (cv[p].x - mu) * rstd * g.x + bb.x;
        vn[p].y = (cv[p].y - mu) * rstd * g.y + bb.y;
        vn[p].z = (cv[p].z - mu) * rstd * g.z + bb.z;
        vn[p].w = (cv[p].w - mu) * rstd * g.w + bb.w;
    }

    if (t < 64) {
        float4 qb = *(const float4*)&q_bias[c];
        float sc = __expf(fminf(logit_scale[t >> 3], 4.6051701859880914f));
        float ss[4];
#pragma unroll
        for (int p = 0; p < 4; p++) {
            vn[p].x += qb.x; vn[p].y += qb.y; vn[p].z += qb.z; vn[p].w += qb.w;
            ss[p] = vn[p].x * vn[p].x + vn[p].y * vn[p].y +
                    vn[p].z * vn[p].z + vn[p].w * vn[p].w;
        }
#pragma unroll
        for (int o = 4; o; o >>= 1)
#pragma unroll
            for (int p = 0; p < 4; p++) ss[p] += __shfl_xor_sync(0xffffffffu, ss[p], o);
#pragma unroll
        for (int p = 0; p < 4; p++) {
            float rn = rsqrtf(fmaxf(ss[p], 1.55e-5f)) * sc;
            float4 o4 = {vn[p].x * rn, vn[p].y * rn, vn[p].z * rn, vn[p].w * rn};
            *(float4*)&qn[(size_t)(pixbase + p) * CH + c] = o4;
        }
    } else if (t < 128) {
        int cc = c - 256;
        float ss[4];
#pragma unroll
        for (int p = 0; p < 4; p++)
            ss[p] = vn[p].x * vn[p].x + vn[p].y * vn[p].y +
                    vn[p].z * vn[p].z + vn[p].w * vn[p].w;
#pragma unroll
        for (int o = 4; o; o >>= 1)
#pragma unroll
            for (int p = 0; p < 4; p++) ss[p] += __shfl_xor_sync(0xffffffffu, ss[p], o);
#pragma unroll
        for (int p = 0; p < 4; p++) {
            float rn = rsqrtf(fmaxf(ss[p], 1.55e-5f));
            float4 o4 = {vn[p].x * rn, vn[p].y * rn, vn[p].z * rn, vn[p].w * rn};
            *(float4*)&kn[(size_t)(pixbase + p) * CH + cc] = o4;
        }
    } else {
        int cc = c - 512;
        float4 vb = *(const float4*)&v_bias[cc];
#pragma unroll
        for (int p = 0; p < 4; p++) {
            float4 o4 = {vn[p].x + vb.x, vn[p].y + vb.y, vn[p].z + vb.z, vn[p].w + vb.w};
            *(float4*)&vv[(size_t)(pixbase + p) * CH + cc] = o4;
        }
    }
}

// ---------------- attention: split-tf32 QK^T, single-tf32 PV, double-buffered K/V staging ----------------
constexpr int A_QSH = 0;                      // [64][36]
constexpr int A_QSL = A_QSH + 64 * 36;        // [64][36]
constexpr int A_KSH = A_QSL + 64 * 36;        // 2 x [32][72]
constexpr int A_KSL = A_KSH + 2 * 32 * 72;    // 2 x [32][72]
constexpr int A_VS  = A_KSL + 2 * 32 * 72;    // 2 x [64][40]
constexpr int A_SP  = A_VS + 2 * 64 * 40;     // [64][68]
constexpr int A_BSM = A_SP + 64 * 68;         // [529]
constexpr int A_LRD = A_BSM + NREL;           // [4][64]
constexpr int A_LFN = A_LRD + 256;            // [64]
constexpr int A_TOT = A_LFN + 64;             // 24145 floats = 96580 B

__global__ __launch_bounds__(256, 2) void attn_kernel(
    const float* __restrict__ qn, const float* __restrict__ kn,
    const float* __restrict__ vv, const float* __restrict__ btab,
    const float* __restrict__ logit_scale, float* __restrict__ out) {
    extern __shared__ float sm[];
    float* QsH = sm + A_QSH;  float* QsL = sm + A_QSL;
    float* KsH = sm + A_KSH;  float* KsL = sm + A_KSL;
    float* Vs  = sm + A_VS;
    float* Sp  = sm + A_SP;
    float* bsm = sm + A_BSM;
    float* lrd = sm + A_LRD;
    float* lfn = sm + A_LFN;

    int w = blockIdx.x, h = blockIdx.y;
    int b = w >> 8, wr = (w >> 4) & 15, wc = w & 15;
    int t = threadIdx.x;
    int warp = t >> 5, lane = t & 31, grp = lane >> 2, thr = lane & 3;
    float bound = __expf(fminf(logit_scale[h], 4.6051701859880914f)) + 16.0f;

    for (int i = t; i < NREL; i += 256) bsm[i] = btab[i * HEADS + h];

    // stage Q (pre-split hi/lo tf32)
    {
        int row = t & 63, d0 = (t >> 6) << 3;
        int py = wr * 8 + (row >> 3), px = wc * 8 + (row & 7);
        const float* qp = qn + (size_t)(((b << 7) | py) << 7 | px) * CH + h * HD + d0;
        float4 a = *(const float4*)qp;
        float4 bq = *(const float4*)(qp + 4);
        float v[8] = {a.x, a.y, a.z, a.w, bq.x, bq.y, bq.z, bq.w};
#pragma unroll
        for (int i = 0; i < 8; i++) {
            unsigned hb, lb;
            split_tf32(v[i], hb, lb);
            QsH[row * 36 + d0 + i] = __uint_as_float(hb);
            QsL[row * 36 + d0 + i] = __uint_as_float(lb);
        }
    }

    // per-thread staging coords (constant across chunks)
    int jst = t & 63, d1 = (t >> 6) << 3;

    // prologue: stage chunk 0 into buffer 0
    {
        int jg = jst;
        int gy = wr * 8 - 4 + (jg >> 4), gx = wc * 8 - 4 + (jg & 15);
        float kv[8] = {0, 0, 0, 0, 0, 0, 0, 0};
        float vvv[8] = {0, 0, 0, 0, 0, 0, 0, 0};
        if ((unsigned)gy < 128u && (unsigned)gx < 128u) {
            size_t gb = (size_t)(((b << 7) | gy) << 7 | gx) * CH + h * HD + d1;
            float4 k0 = *(const float4*)(kn + gb), k1 = *(const float4*)(kn + gb + 4);
            float4 v0 = *(const float4*)(vv + gb), v1 = *(const float4*)(vv + gb + 4);
            kv[0] = k0.x; kv[1] = k0.y; kv[2] = k0.z; kv[3] = k0.w;
            kv[4] = k1.x; kv[5] = k1.y; kv[6] = k1.z; kv[7] = k1.w;
            vvv[0] = v0.x; vvv[1] = v0.y; vvv[2] = v0.z; vvv[3] = v0.w;
            vvv[4] = v1.x; vvv[5] = v1.y; vvv[6] = v1.z; vvv[7] = v1.w;
        }
#pragma unroll
        for (int i = 0; i < 8; i++) {
            unsigned hb, lb;
            split_tf32(kv[i], hb, lb);
            KsH[(d1 + i) * 72 + jst] = __uint_as_float(hb);
            KsL[(d1 + i) * 72 + jst] = __uint_as_float(lb);
        }
        float vh[8];
#pragma unroll
        for (int i = 0; i < 8; i++) vh[i] = __uint_as_float(f2tf32(vvv[i]));
        *(float4*)&Vs[jst * 40 + d1]     = *(float4*)&vh[0];
        *(float4*)&Vs[jst * 40 + d1 + 4] = *(float4*)&vh[4];
    }
    __syncthreads();

    int wmA = (warp & 1) * 32, wnA = (warp >> 1) * 16;
    int mB = warp & 3, nB = warp >> 2;

    float oacc[2][4];
#pragma unroll
    for (int nt = 0; nt < 2; nt++)
#pragma unroll
        for (int r = 0; r < 4; r++) oacc[nt][r] = 0.0f;
    float rs[4] = {0.0f, 0.0f, 0.0f, 0.0f};

    for (int c0 = 0; c0 < 4; c0++) {
        int buf = c0 & 1, nbuf = buf ^ 1;
        bool have_next = (c0 < 3);

        // next-chunk gmem base (shared by K and V loads)
        size_t gbN = 0;
        bool okN = false;
        if (have_next) {
            int jgN = ((c0 + 1) << 6) + jst;
            int gy = wr * 8 - 4 + (jgN >> 4), gx = wc * 8 - 4 + (jgN & 15);
            okN = (unsigned)gy < 128u && (unsigned)gx < 128u;
            if (okN) gbN = (size_t)(((b << 7) | gy) << 7 | gx) * CH + h * HD + d1;
        }

        // issue next K loads (latency hidden by QK^T below)
        float kvN[8] = {0, 0, 0, 0, 0, 0, 0, 0};
        if (okN) {
            float4 k0 = *(const float4*)(kn + gbN), k1 = *(const float4*)(kn + gbN + 4);
            kvN[0] = k0.x; kvN[1] = k0.y; kvN[2] = k0.z; kvN[3] = k0.w;
            kvN[4] = k1.x; kvN[5] = k1.y; kvN[6] = k1.z; kvN[7] = k1.w;
        }

        // ---- QK^T: S[32x16] per warp, split-tf32 (3 mma each) ----
        const unsigned* QH = (const unsigned*)QsH;
        const unsigned* QL = (const unsigned*)QsL;
        const unsigned* KH = (const unsigned*)(KsH + buf * (32 * 72));
        const unsigned* KL = (const unsigned*)(KsL + buf * (32 * 72));
        float acc[2][2][4];
#pragma unroll
        for (int mt = 0; mt < 2; mt++)
#pragma unroll
            for (int nt = 0; nt < 2; nt++)
#pragma unroll
                for (int r = 0; r < 4; r++) acc[mt][nt][r] = 0.0f;
#pragma unroll
        for (int ks = 0; ks < 4; ks++) {
            int kb = ks * 8;
            unsigned aH[2][4], aL[2][4], bH[2][2], bL[2][2];
#pragma unroll
            for (int mt = 0; mt < 2; mt++) {
                int r0 = wmA + mt * 16 + grp;
                int ca = kb + thr;
                aH[mt][0] = QH[r0 * 36 + ca];       aH[mt][1] = QH[(r0 + 8) * 36 + ca];
                aH[mt][2] = QH[r0 * 36 + ca + 4];   aH[mt][3] = QH[(r0 + 8) * 36 + ca + 4];
                aL[mt][0] = QL[r0 * 36 + ca];       aL[mt][1] = QL[(r0 + 8) * 36 + ca];
                aL[mt][2] = QL[r0 * 36 + ca + 4];   aL[mt][3] = QL[(r0 + 8) * 36 + ca + 4];
            }
#pragma unroll
            for (int nt = 0; nt < 2; nt++) {
                int nc = wnA + nt * 8 + grp;
                bH[nt][0] = KH[(kb + thr) * 72 + nc];
                bH[nt][1] = KH[(kb + thr + 4) * 72 + nc];
                bL[nt][0] = KL[(kb + thr) * 72 + nc];
                bL[nt][1] = KL[(kb + thr + 4) * 72 + nc];
            }
#pragma unroll
            for (int mt = 0; mt < 2; mt++)
#pragma unroll
                for (int nt = 0; nt < 2; nt++) {
                    MMA_TF32(acc[mt][nt], aH[mt][0], aH[mt][1], aH[mt][2], aH[mt][3],
                             bH[nt][0], bH[nt][1]);
                    MMA_TF32(acc[mt][nt], aH[mt][0], aH[mt][1], aH[mt][2], aH[mt][3],
                             bL[nt][0], bL[nt][1]);
                    MMA_TF32(acc[mt][nt], aL[mt][0], aL[mt][1], aL[mt][2], aL[mt][3],
                             bH[nt][0], bH[nt][1]);
                }
        }

        // ---- bias + exp + P store (tf32-rounded) + row-sum accum ----
        int cbg = c0 << 6;
#pragma unroll
        for (int mt = 0; mt < 2; mt++) {
            int r0 = wmA + mt * 16 + grp, r1 = r0 + 8;
            int q0 = (r0 >> 3) * 23 + (r0 & 7);
            int q1 = (r1 >> 3) * 23 + (r1 & 7);
#pragma unroll
            for (int nt = 0; nt < 2; nt++) {
                int lc = wnA + nt * 8 + 2 * thr;
                int jg0 = cbg + lc, jg1 = jg0 + 1;
                int b0 = (15 - (jg0 >> 4)) * 23 + (15 - (jg0 & 15));
                int b1 = (15 - (jg1 >> 4)) * 23 + (15 - (jg1 & 15));
                float p00 = __expf(acc[mt][nt][0] - bound + bsm[b0 + q0]);
                float p01 = __expf(acc[mt][nt][1] - bound + bsm[b1 + q0]);
                float p10 = __expf(acc[mt][nt][2] - bound + bsm[b0 + q1]);
                float p11 = __expf(acc[mt][nt][3] - bound + bsm[b1 + q1]);
                rs[mt * 2]     += p00 + p01;
                rs[mt * 2 + 1] += p10 + p11;
                float2 w0 = {__uint_as_float(f2tf32(p00)), __uint_as_float(f2tf32(p01))};
                float2 w1 = {__uint_as_float(f2tf32(p10)), __uint_as_float(f2tf32(p11))};
                *(float2*)&Sp[r0 * 68 + lc] = w0;
                *(float2*)&Sp[r1 * 68 + lc] = w1;
            }
        }
        __syncthreads();   // Sp visible for PV

        // issue next V loads (latency hidden by PV below)
        float vvN[8] = {0, 0, 0, 0, 0, 0, 0, 0};
        if (okN) {
            float4 v0 = *(const float4*)(vv + gbN), v1 = *(const float4*)(vv + gbN + 4);
            vvN[0] = v0.x; vvN[1] = v0.y; vvN[2] = v0.z; vvN[3] = v0.w;
            vvN[4] = v1.x; vvN[5] = v1.y; vvN[6] = v1.z; vvN[7] = v1.w;
        }

        // ---- PV: O[16x16] per warp, single tf32 mma ----
        const unsigned* SPu = (const unsigned*)Sp;
        const unsigned* VU  = (const unsigned*)(Vs + buf * (64 * 40));
        int ra = mB * 16 + grp;
#pragma unroll
        for (int ks = 0; ks < 8; ks++) {
            int kb = ks * 8;
            unsigned a0 = SPu[ra * 68 + kb + thr];
            unsigned a1 = SPu[(ra + 8) * 68 + kb + thr];
            unsigned a2 = SPu[ra * 68 + kb + thr + 4];
            unsigned a3 = SPu[(ra + 8) * 68 + kb + thr + 4];
#pragma unroll
            for (int nt = 0; nt < 2; nt++) {
                int col = nB * 16 + nt * 8 + grp;
                unsigned b0 = VU[(kb + thr) * 40 + col];
                unsigned b1 = VU[(kb + thr + 4) * 40 + col];
                MMA_TF32(oacc[nt], a0, a1, a2, a3, b0, b1);
            }
        }

        // ---- stage next chunk into the idle buffer ----
        if (have_next) {
            float* KHn = KsH + nbuf * (32 * 72);
            float* KLn = KsL + nbuf * (32 * 72);
            float* Vn  = Vs  + nbuf * (64 * 40);
#pragma unroll
            for (int i = 0; i < 8; i++) {
                unsigned hb, lb;
                split_tf32(kvN[i], hb, lb);
                KHn[(d1 + i) * 72 + jst] = __uint_as_float(hb);
                KLn[(d1 + i) * 72 + jst] = __uint_as_float(lb);
            }
            float vh[8];
#pragma unroll
            for (int i = 0; i < 8; i++) vh[i] = __uint_as_float(f2tf32(vvN[i]));
            *(float4*)&Vn[jst * 40 + d1]     = *(float4*)&vh[0];
            *(float4*)&Vn[jst * 40 + d1 + 4] = *(float4*)&vh[4];
        }
        __syncthreads();   // staged data visible; Sp safe to overwrite next iter
    }

    // ---- row-sum reduction ----
#pragma unroll
    for (int i = 0; i < 4; i++) {
        rs[i] += __shfl_xor_sync(0xffffffffu, rs[i], 1);
        rs[i] += __shfl_xor_sync(0xffffffffu, rs[i], 2);
    }
    if (thr == 0) {
#pragma unroll
        for (int mt = 0; mt < 2; mt++) {
#pragma unroll
            for (int hh = 0; hh < 2; hh++) {
                int row = wmA + mt * 16 + hh * 8 + grp;
                lrd[(warp >> 1) * 64 + row] = rs[mt * 2 + hh];
            }
        }
    }
    __syncthreads();
    if (t < 64)
        lfn[t] = 1.0f / (lrd[t] + lrd[64 + t] + lrd[128 + t] + lrd[192 + t]);
    __syncthreads();

    // ---- normalize + write ----
    {
        int r0 = mB * 16 + grp, r1 = r0 + 8;
        float inv0 = lfn[r0], inv1 = lfn[r1];
        int py0 = wr * 8 + (r0 >> 3), px0 = wc * 8 + (r0 & 7);
        int py1 = wr * 8 + (r1 >> 3), px1 = wc * 8 + (r1 & 7);
        float* op0 = out + (size_t)(((b << 7) | py0) << 7 | px0) * CH + h * HD;
        float* op1 = out + (size_t)(((b << 7) | py1) << 7 | px1) * CH + h * HD;
#pragma unroll
        for (int nt = 0; nt < 2; nt++) {
            int col = nB * 16 + nt * 8 + 2 * thr;
            float2 w0 = {oacc[nt][0] * inv0, oacc[nt][1] * inv0};
            float2 w1 = {oacc[nt][2] * inv1, oacc[nt][3] * inv1};
            *(float2*)(op0 + col) = w0;
            *(float2*)(op1 + col) = w1;
        }
    }
}

// ---------------- launch ----------------
extern "C" void kernel_launch(void* const* d_in, const int* in_sizes, int n_in,
                              void* d_out, int out_size) {
    const float* x           = (const float*)d_in[0];
    const float* w_qkv       = (const float*)d_in[1];
    const float* w_dw        = (const float*)d_in[2];
    const float* ln_g        = (const float*)d_in[3];
    const float* ln_b        = (const float*)d_in[4];
    const float* q_bias      = (const float*)d_in[5];
    const float* v_bias      = (const float*)d_in[6];
    const float* logit_scale = (const float*)d_in[7];
    const float* cpb_w1      = (const float*)d_in[8];
    const float* cpb_b1      = (const float*)d_in[9];
    const float* cpb_w2      = (const float*)d_in[10];
    const float* w_proj      = (const float*)d_in[11];
    float* out = (float*)d_out;

    float *qkv, *qn, *kn, *vv, *att, *btab;
    cudaGetSymbolAddress((void**)&qkv,  g_qkv);
    cudaGetSymbolAddress((void**)&qn,   g_qn);
    cudaGetSymbolAddress((void**)&kn,   g_kn);
    cudaGetSymbolAddress((void**)&vv,   g_v);
    cudaGetSymbolAddress((void**)&att,  g_att);
    cudaGetSymbolAddress((void**)&btab, g_btab);

    int smem_attn = A_TOT * 4;
    cudaFuncSetAttribute(attn_kernel, cudaFuncAttributeMaxDynamicSharedMemorySize, smem_attn);
    cudaFuncSetAttribute(mma_gemm, cudaFuncAttributeMaxDynamicSharedMemorySize, GEMM_SMEM);

    cpb_kernel<<<NREL, 256>>>(cpb_w1, cpb_b1, cpb_w2, btab);
    mma_gemm<<<dim3(C3 / 128, NPIX / 128), 256, GEMM_SMEM>>>(NPIX, C3, CH, x, w_qkv, qkv);
    conv_ln_kernel<<<NPIX / 4, 192>>>(qkv, w_dw, ln_g, ln_b, q_bias, v_bias, logit_scale,
                                      qn, kn, vv);
    attn_kernel<<<dim3(512, 8), 256, smem_attn>>>(qn, kn, vv, btab, logit_scale, att);
    mma_gemm<<<dim3(CH / 128, NPIX / 128), 256, GEMM_SMEM>>>(NPIX, CH, CH, att, w_proj, out);
}

// round 15
// speedup vs baseline: 1.1952x; 1.1233x over previous
#include <cuda_runtime.h>
#include <math.h>
#include <stdint.h>

// ---------------- problem constants ----------------
constexpr int BATCH = 2, HH = 128, WW = 128, CH = 256;
constexpr int HEADS = 8, HD = 32;
constexpr int NPIX = BATCH * HH * WW;   // 32768
constexpr int C3 = 3 * CH;              // 768
constexpr int NREL = 23 * 23;           // 529

// ---------------- device scratch (allocation-free) ----------------
__device__ float g_qkv[NPIX * C3];
__device__ float g_qn [NPIX * CH];
__device__ float g_kn [NPIX * CH];
__device__ float g_v  [NPIX * CH];
__device__ float g_att[NPIX * CH];   // holds tf32-rounded x early, attention output later
__device__ float g_btab[NREL * HEADS];
__device__ float g_wq[CH * C3];      // tf32-rounded w_qkv
__device__ float g_wp[CH * CH];      // tf32-rounded w_proj

// ---------------- tf32 helpers ----------------
__device__ __forceinline__ unsigned f2tf32(float x) {
    unsigned r;
    asm("cvt.rna.tf32.f32 %0, %1;" : "=r"(r) : "f"(x));
    return r;
}
__device__ __forceinline__ void split_tf32(float x, unsigned& hi, unsigned& lo) {
    hi = f2tf32(x);
    lo = f2tf32(x - __uint_as_float(hi));
}
#define MMA_TF32(C, A0, A1, A2, A3, B0, B1)                                    \
    asm volatile(                                                              \
        "mma.sync.aligned.m16n8k8.row.col.f32.tf32.tf32.f32 "                  \
        "{%0,%1,%2,%3}, {%4,%5,%6,%7}, {%8,%9}, {%0,%1,%2,%3};"                \
        : "+f"((C)[0]), "+f"((C)[1]), "+f"((C)[2]), "+f"((C)[3])               \
        : "r"(A0), "r"(A1), "r"(A2), "r"(A3), "r"(B0), "r"(B1))

__device__ __forceinline__ uint32_t smem_u32(const void* p) {
    uint32_t a;
    asm("{ .reg .u64 tmp; cvta.to.shared.u64 tmp, %1; cvt.u32.u64 %0, tmp; }"
        : "=r"(a) : "l"(p));
    return a;
}
__device__ __forceinline__ void cp_async16(uint32_t saddr, const void* gaddr) {
    asm volatile("cp.async.cg.shared.global [%0], [%1], 16;"
                 :: "r"(saddr), "l"(gaddr) : "memory");
}
#define CP_COMMIT() asm volatile("cp.async.commit_group;" ::: "memory")
#define CP_WAIT(n)  asm volatile("cp.async.wait_group %0;" :: "n"(n) : "memory")

// ---------------- elementwise tf32 rounding pass ----------------
__global__ void round_tf32_kernel(const float* __restrict__ src,
                                  float* __restrict__ dst, int n4) {
    int i = blockIdx.x * blockDim.x + threadIdx.x;
    if (i < n4) {
        float4 v = ((const float4*)src)[i];
        v.x = __uint_as_float(f2tf32(v.x));
        v.y = __uint_as_float(f2tf32(v.y));
        v.z = __uint_as_float(f2tf32(v.z));
        v.w = __uint_as_float(f2tf32(v.w));
        ((float4*)dst)[i] = v;
    }
}

// ---------------- CPB relative-bias MLP ----------------
__device__ __forceinline__ float relcoord(int r) {
    float cs = (float)(r - 11) * (8.0f / 7.0f);
    float a = log1pf(fabsf(cs)) * (1.0f / 2.0794415416798357f);
    return cs > 0.0f ? a : (cs < 0.0f ? -a : 0.0f);
}

__global__ void cpb_kernel(const float* __restrict__ w1, const float* __restrict__ b1,
                           const float* __restrict__ w2, float* __restrict__ btab) {
    int i = blockIdx.x;
    float y0 = relcoord(i / 23), y1 = relcoord(i % 23);
    int t = threadIdx.x;
    float part[HEADS];
#pragma unroll
    for (int hh = 0; hh < HEADS; hh++) part[hh] = 0.0f;
    for (int j = t; j < 512; j += 256) {
        float hv = fmaf(y0, w1[j], fmaf(y1, w1[512 + j], b1[j]));
        hv = fmaxf(hv, 0.0f);
#pragma unroll
        for (int hh = 0; hh < HEADS; hh++) part[hh] = fmaf(hv, w2[j * HEADS + hh], part[hh]);
    }
#pragma unroll
    for (int hh = 0; hh < HEADS; hh++)
#pragma unroll
        for (int o = 16; o; o >>= 1) part[hh] += __shfl_xor_sync(0xffffffffu, part[hh], o);
    __shared__ float sm[HEADS][8];
    int lane = t & 31, wrp = t >> 5;
    if (lane == 0)
        for (int hh = 0; hh < HEADS; hh++) sm[hh][wrp] = part[hh];
    __syncthreads();
    if (t < HEADS) {
        float ssum = 0.0f;
        for (int k = 0; k < 8; k++) ssum += sm[t][k];
        btab[i * HEADS + t] = 16.0f / (1.0f + expf(-ssum));
    }
}

// ---------------- tf32 GEMM: cp.async staging, BK=32, 2 blocks/SM ----------------
// operands must be pre-rounded to tf32 in gmem (mma truncation is then exact).
constexpr int GBM = 128, GBN = 128, GBK = 32, GK = 256;
constexpr int AST = GBK + 4;   // 36: A frag bank = (4*grp+thr)%32, all distinct
constexpr int BST = GBN + 8;   // 136: B frag bank = (8*thr+grp)%32, all distinct
constexpr int ABUF = GBM * AST;   // 4608 words
constexpr int BBUF = GBK * BST;   // 4352 words
constexpr int GEMM_SMEM = 2 * (ABUF + BBUF) * 4;  // 71680 bytes

__global__ __launch_bounds__(256, 2) void mma_gemm(int M, int N,
                                                   const float* __restrict__ A,
                                                   const float* __restrict__ B,
                                                   float* __restrict__ C) {
    extern __shared__ float smf[];
    uint32_t sbase = smem_u32(smf);

    int tid = threadIdx.x;
    int warp = tid >> 5, lane = tid & 31;
    int wm = (warp & 1) * 64, wn = (warp >> 1) * 32;
    int brow = blockIdx.y * GBM, bcol = blockIdx.x * GBN;
    int grp = lane >> 2, thr = lane & 3;

    float acc[4][4][4];
#pragma unroll
    for (int i = 0; i < 4; i++)
#pragma unroll
        for (int j = 0; j < 4; j++)
#pragma unroll
            for (int r = 0; r < 4; r++) acc[i][j][r] = 0.0f;

    int aRow = tid >> 1, aCol = (tid & 1) << 4;     // A: 128 rows x 32 cols, 16 floats/thread
    int bRow = tid >> 3, bCol = (tid & 7) << 4;     // B: 32 rows x 128 cols, 16 floats/thread

    const float* Ap = A + (size_t)(brow + aRow) * GK + aCol;
    const float* Bp = B + (size_t)bRow * N + bcol + bCol;
    uint32_t asA = sbase + (uint32_t)(aRow * AST + aCol) * 4;
    uint32_t asB = sbase + (uint32_t)(2 * ABUF + bRow * BST + bCol) * 4;

    constexpr int niter = GK / GBK;   // 8

    // prologue: stage chunk 0 into buffer 0
    {
        const float* ag = Ap;
        cp_async16(asA, ag);      cp_async16(asA + 16, ag + 4);
        cp_async16(asA + 32, ag + 8); cp_async16(asA + 48, ag + 12);
        const float* bg = Bp;
        cp_async16(asB, bg);      cp_async16(asB + 16, bg + 4);
        cp_async16(asB + 32, bg + 8); cp_async16(asB + 48, bg + 12);
        CP_COMMIT();
    }

    for (int iter = 0; iter < niter; iter++) {
        int buf = iter & 1;
        if (iter + 1 < niter) {
            int nb = buf ^ 1;
            uint32_t aA = asA + (uint32_t)(nb * ABUF) * 4;
            uint32_t aB = asB + (uint32_t)(nb * BBUF) * 4;
            const float* ag = Ap + (iter + 1) * GBK;
            cp_async16(aA, ag);       cp_async16(aA + 16, ag + 4);
            cp_async16(aA + 32, ag + 8);  cp_async16(aA + 48, ag + 12);
            const float* bg = Bp + (size_t)(iter + 1) * GBK * N;
            cp_async16(aB, bg);       cp_async16(aB + 16, bg + 4);
            cp_async16(aB + 32, bg + 8);  cp_async16(aB + 48, bg + 12);
            CP_COMMIT();
            CP_WAIT(1);
        } else {
            CP_WAIT(0);
        }
        __syncthreads();

        const unsigned* Acur = (const unsigned*)(smf + buf * ABUF);
        const unsigned* Bcur = (const unsigned*)(smf + 2 * ABUF + buf * BBUF);
#pragma unroll
        for (int kstep = 0; kstep < 4; kstep++) {
            int kb = kstep * 8;
            unsigned a[4][4], bfr[4][2];
#pragma unroll
            for (int mt = 0; mt < 4; mt++) {
                int r0 = wm + mt * 16 + grp;
                int ca = kb + thr;
                a[mt][0] = Acur[r0 * AST + ca];
                a[mt][1] = Acur[(r0 + 8) * AST + ca];
                a[mt][2] = Acur[r0 * AST + ca + 4];
                a[mt][3] = Acur[(r0 + 8) * AST + ca + 4];
            }
#pragma unroll
            for (int nt = 0; nt < 4; nt++) {
                int kr = kb + thr;
                int nc = wn + nt * 8 + grp;
                bfr[nt][0] = Bcur[kr * BST + nc];
                bfr[nt][1] = Bcur[(kr + 4) * BST + nc];
            }
#pragma unroll
            for (int mt = 0; mt < 4; mt++)
#pragma unroll
                for (int nt = 0; nt < 4; nt++)
                    MMA_TF32(acc[mt][nt], a[mt][0], a[mt][1], a[mt][2], a[mt][3],
                             bfr[nt][0], bfr[nt][1]);
        }
        __syncthreads();
    }

#pragma unroll
    for (int mt = 0; mt < 4; mt++) {
#pragma unroll
        for (int nt = 0; nt < 4; nt++) {
            int row = brow + wm + mt * 16 + grp;
            int col = bcol + wn + nt * 8 + thr * 2;
            float2 v0 = {acc[mt][nt][0], acc[mt][nt][1]};
            float2 v1 = {acc[mt][nt][2], acc[mt][nt][3]};
            *(float2*)(C + (size_t)row * N + col) = v0;
            *(float2*)(C + (size_t)(row + 8) * N + col) = v1;
        }
    }
}

// ---------------- conv + LN + biases + l2norm: 4 px/block, 192 threads (R12 exact) ----------------
__global__ __launch_bounds__(192) void conv_ln_kernel(
    const float* __restrict__ qkv, const float* __restrict__ wdw,
    const float* __restrict__ ln_g, const float* __restrict__ ln_b,
    const float* __restrict__ q_bias, const float* __restrict__ v_bias,
    const float* __restrict__ logit_scale,
    float* __restrict__ qn, float* __restrict__ kn, float* __restrict__ vv) {
    int pixbase = blockIdx.x << 2;
    int b = pixbase >> 14, y = (pixbase >> 7) & 127, x0 = pixbase & 127;
    int t = threadIdx.x;
    int c = t << 2;

    float4 wv[9];
#pragma unroll
    for (int i = 0; i < 9; i++) wv[i] = *(const float4*)&wdw[i * C3 + c];

    float4 cv[4];
#pragma unroll
    for (int p = 0; p < 4; p++) cv[p] = make_float4(0.f, 0.f, 0.f, 0.f);

#pragma unroll
    for (int dy = 0; dy < 3; dy++) {
        int yy = y + dy - 1;
        if ((unsigned)yy >= (unsigned)HH) continue;
        float4 rv[6];
#pragma unroll
        for (int dx = 0; dx < 6; dx++) {
            int xx = x0 + dx - 1;
            if ((unsigned)xx < (unsigned)WW)
                rv[dx] = *(const float4*)&qkv[(size_t)(((b << 7) | yy) << 7 | xx) * C3 + c];
            else
                rv[dx] = make_float4(0.f, 0.f, 0.f, 0.f);
        }
#pragma unroll
        for (int p = 0; p < 4; p++) {
#pragma unroll
            for (int kx = 0; kx < 3; kx++) {
                float4 wk = wv[dy * 3 + kx];
                float4 xv = rv[p + kx];
                cv[p].x = fmaf(wk.x, xv.x, cv[p].x);
                cv[p].y = fmaf(wk.y, xv.y, cv[p].y);
                cv[p].z = fmaf(wk.z, xv.z, cv[p].z);
                cv[p].w = fmaf(wk.w, xv.w, cv[p].w);
            }
        }
    }

    float s[4], s2[4];
#pragma unroll
    for (int p = 0; p < 4; p++) {
        s[p]  = cv[p].x + cv[p].y + cv[p].z + cv[p].w;
        s2[p] = cv[p].x * cv[p].x + cv[p].y * cv[p].y + cv[p].z * cv[p].z + cv[p].w * cv[p].w;
    }
#pragma unroll
    for (int o = 16; o; o >>= 1) {
#pragma unroll
        for (int p = 0; p < 4; p++) {
            s[p]  += __shfl_xor_sync(0xffffffffu, s[p], o);
            s2[p] += __shfl_xor_sync(0xffffffffu, s2[p], o);
        }
    }
    __shared__ float ws[6][4], ws2[6][4];
    __shared__ float s_mu[4], s_rstd[4];
    int lane = t & 31, wrp = t >> 5;
    if (lane == 0) {
#pragma unroll
        for (int p = 0; p < 4; p++) { ws[wrp][p] = s[p]; ws2[wrp][p] = s2[p]; }
    }
    __syncthreads();
    if (t < 32) {
        int p = t >> 3, j = t & 7;
        float a1 = (j < 6) ? ws[j][p]  : 0.0f;
        float a2 = (j < 6) ? ws2[j][p] : 0.0f;
#pragma unroll
        for (int o = 4; o; o >>= 1) {
            a1 += __shfl_xor_sync(0xffffffffu, a1, o);
            a2 += __shfl_xor_sync(0xffffffffu, a2, o);
        }
        if (j == 0) {
            float mu = a1 * (1.0f / 768.0f);
            float var = a2 * (1.0f / 768.0f) - mu * mu;
            s_mu[p] = mu;
            s_rstd[p] = rsqrtf(var + 1e-5f);
        }
    }
    __syncthreads();

    float4 g  = *(const float4*)&ln_g[c];
    float4 bb = *(const float4*)&ln_b[c];
    float4 vn[4];
#pragma unroll
    for (int p = 0; p < 4; p++) {
        float mu = s_mu[p], rstd = s_rstd[p];
        vn[p].x = (cv[p].x - mu) * rstd * g.x + bb.x;
        vn[p].y = (cv[p].y - mu) * rstd * g.y + bb.y;
        vn[p].z = (cv[p].z - mu) * rstd * g.z + bb.z;
        vn[p].w = (cv[p].w - mu) * rstd * g.w + bb.w;
    }

    if (t < 64) {
        float4 qb = *(const float4*)&q_bias[c];
        float sc = __expf(fminf(logit_scale[t >> 3], 4.6051701859880914f));
        float ss[4];
#pragma unroll
        for (int p = 0; p < 4; p++) {
            vn[p].x += qb.x; vn[p].y += qb.y; vn[p].z += qb.z; vn[p].w += qb.w;
            ss[p] = vn[p].x * vn[p].x + vn[p].y * vn[p].y +
                    vn[p].z * vn[p].z + vn[p].w * vn[p].w;
        }
#pragma unroll
        for (int o = 4; o; o >>= 1)
#pragma unroll
            for (int p = 0; p < 4; p++) ss[p] += __shfl_xor_sync(0xffffffffu, ss[p], o);
#pragma unroll
        for (int p = 0; p < 4; p++) {
            float rn = rsqrtf(fmaxf(ss[p], 1.55e-5f)) * sc;
            float4 o4 = {vn[p].x * rn, vn[p].y * rn, vn[p].z * rn, vn[p].w * rn};
            *(float4*)&qn[(size_t)(pixbase + p) * CH + c] = o4;
        }
    } else if (t < 128) {
        int cc = c - 256;
        float ss[4];
#pragma unroll
        for (int p = 0; p < 4; p++)
            ss[p] = vn[p].x * vn[p].x + vn[p].y * vn[p].y +
                    vn[p].z * vn[p].z + vn[p].w * vn[p].w;
#pragma unroll
        for (int o = 4; o; o >>= 1)
#pragma unroll
            for (int p = 0; p < 4; p++) ss[p] += __shfl_xor_sync(0xffffffffu, ss[p], o);
#pragma unroll
        for (int p = 0; p < 4; p++) {
            float rn = rsqrtf(fmaxf(ss[p], 1.55e-5f));
            float4 o4 = {vn[p].x * rn, vn[p].y * rn, vn[p].z * rn, vn[p].w * rn};
            *(float4*)&kn[(size_t)(pixbase + p) * CH + cc] = o4;
        }
    } else {
        int cc = c - 512;
        float4 vb = *(const float4*)&v_bias[cc];
#pragma unroll
        for (int p = 0; p < 4; p++) {
            float4 o4 = {vn[p].x + vb.x, vn[p].y + vb.y, vn[p].z + vb.z, vn[p].w + vb.w};
            *(float4*)&vv[(size_t)(pixbase + p) * CH + cc] = o4;
        }
    }
}

// ---------------- attention (R12: split-tf32 QK^T, single-tf32 PV, db K/V; out pre-rounded) ----------------
constexpr int A_QSH = 0;
constexpr int A_QSL = A_QSH + 64 * 36;
constexpr int A_KSH = A_QSL + 64 * 36;
constexpr int A_KSL = A_KSH + 2 * 32 * 72;
constexpr int A_VS  = A_KSL + 2 * 32 * 72;
constexpr int A_SP  = A_VS + 2 * 64 * 40;
constexpr int A_BSM = A_SP + 64 * 68;
constexpr int A_LRD = A_BSM + NREL;
constexpr int A_LFN = A_LRD + 256;
constexpr int A_TOT = A_LFN + 64;

__global__ __launch_bounds__(256, 2) void attn_kernel(
    const float* __restrict__ qn, const float* __restrict__ kn,
    const float* __restrict__ vv, const float* __restrict__ btab,
    const float* __restrict__ logit_scale, float* __restrict__ out) {
    extern __shared__ float sm[];
    float* QsH = sm + A_QSH;  float* QsL = sm + A_QSL;
    float* KsH = sm + A_KSH;  float* KsL = sm + A_KSL;
    float* Vs  = sm + A_VS;
    float* Sp  = sm + A_SP;
    float* bsm = sm + A_BSM;
    float* lrd = sm + A_LRD;
    float* lfn = sm + A_LFN;

    int w = blockIdx.x, h = blockIdx.y;
    int b = w >> 8, wr = (w >> 4) & 15, wc = w & 15;
    int t = threadIdx.x;
    int warp = t >> 5, lane = t & 31, grp = lane >> 2, thr = lane & 3;
    float bound = __expf(fminf(logit_scale[h], 4.6051701859880914f)) + 16.0f;

    for (int i = t; i < NREL; i += 256) bsm[i] = btab[i * HEADS + h];

    {
        int row = t & 63, d0 = (t >> 6) << 3;
        int py = wr * 8 + (row >> 3), px = wc * 8 + (row & 7);
        const float* qp = qn + (size_t)(((b << 7) | py) << 7 | px) * CH + h * HD + d0;
        float4 a = *(const float4*)qp;
        float4 bq = *(const float4*)(qp + 4);
        float v[8] = {a.x, a.y, a.z, a.w, bq.x, bq.y, bq.z, bq.w};
#pragma unroll
        for (int i = 0; i < 8; i++) {
            unsigned hb, lb;
            split_tf32(v[i], hb, lb);
            QsH[row * 36 + d0 + i] = __uint_as_float(hb);
            QsL[row * 36 + d0 + i] = __uint_as_float(lb);
        }
    }

    int jst = t & 63, d1 = (t >> 6) << 3;

    {
        int jg = jst;
        int gy = wr * 8 - 4 + (jg >> 4), gx = wc * 8 - 4 + (jg & 15);
        float kv[8] = {0, 0, 0, 0, 0, 0, 0, 0};
        float vvv[8] = {0, 0, 0, 0, 0, 0, 0, 0};
        if ((unsigned)gy < 128u && (unsigned)gx < 128u) {
            size_t gb = (size_t)(((b << 7) | gy) << 7 | gx) * CH + h * HD + d1;
            float4 k0 = *(const float4*)(kn + gb), k1 = *(const float4*)(kn + gb + 4);
            float4 v0 = *(const float4*)(vv + gb), v1 = *(const float4*)(vv + gb + 4);
            kv[0] = k0.x; kv[1] = k0.y; kv[2] = k0.z; kv[3] = k0.w;
            kv[4] = k1.x; kv[5] = k1.y; kv[6] = k1.z; kv[7] = k1.w;
            vvv[0] = v0.x; vvv[1] = v0.y; vvv[2] = v0.z; vvv[3] = v0.w;
            vvv[4] = v1.x; vvv[5] = v1.y; vvv[6] = v1.z; vvv[7] = v1.w;
        }
#pragma unroll
        for (int i = 0; i < 8; i++) {
            unsigned hb, lb;
            split_tf32(kv[i], hb, lb);
            KsH[(d1 + i) * 72 + jst] = __uint_as_float(hb);
            KsL[(d1 + i) * 72 + jst] = __uint_as_float(lb);
        }
        float vh[8];
#pragma unroll
        for (int i = 0; i < 8; i++) vh[i] = __uint_as_float(f2tf32(vvv[i]));
        *(float4*)&Vs[jst * 40 + d1]     = *(float4*)&vh[0];
        *(float4*)&Vs[jst * 40 + d1 + 4] = *(float4*)&vh[4];
    }
    __syncthreads();

    int wmA = (warp & 1) * 32, wnA = (warp >> 1) * 16;
    int mB = warp & 3, nB = warp >> 2;

    float oacc[2][4];
#pragma unroll
    for (int nt = 0; nt < 2; nt++)
#pragma unroll
        for (int r = 0; r < 4; r++) oacc[nt][r] = 0.0f;
    float rs[4] = {0.0f, 0.0f, 0.0f, 0.0f};

    for (int c0 = 0; c0 < 4; c0++) {
        int buf = c0 & 1, nbuf = buf ^ 1;
        bool have_next = (c0 < 3);

        size_t gbN = 0;
        bool okN = false;
        if (have_next) {
            int jgN = ((c0 + 1) << 6) + jst;
            int gy = wr * 8 - 4 + (jgN >> 4), gx = wc * 8 - 4 + (jgN & 15);
            okN = (unsigned)gy < 128u && (unsigned)gx < 128u;
            if (okN) gbN = (size_t)(((b << 7) | gy) << 7 | gx) * CH + h * HD + d1;
        }

        float kvN[8] = {0, 0, 0, 0, 0, 0, 0, 0};
        if (okN) {
            float4 k0 = *(const float4*)(kn + gbN), k1 = *(const float4*)(kn + gbN + 4);
            kvN[0] = k0.x; kvN[1] = k0.y; kvN[2] = k0.z; kvN[3] = k0.w;
            kvN[4] = k1.x; kvN[5] = k1.y; kvN[6] = k1.z; kvN[7] = k1.w;
        }

        const unsigned* QH = (const unsigned*)QsH;
        const unsigned* QL = (const unsigned*)QsL;
        const unsigned* KH = (const unsigned*)(KsH + buf * (32 * 72));
        const unsigned* KL = (const unsigned*)(KsL + buf * (32 * 72));
        float acc[2][2][4];
#pragma unroll
        for (int mt = 0; mt < 2; mt++)
#pragma unroll
            for (int nt = 0; nt < 2; nt++)
#pragma unroll
                for (int r = 0; r < 4; r++) acc[mt][nt][r] = 0.0f;
#pragma unroll
        for (int ks = 0; ks < 4; ks++) {
            int kb = ks * 8;
            unsigned aH[2][4], aL[2][4], bH[2][2], bL[2][2];
#pragma unroll
            for (int mt = 0; mt < 2; mt++) {
                int r0 = wmA + mt * 16 + grp;
                int ca = kb + thr;
                aH[mt][0] = QH[r0 * 36 + ca];       aH[mt][1] = QH[(r0 + 8) * 36 + ca];
                aH[mt][2] = QH[r0 * 36 + ca + 4];   aH[mt][3] = QH[(r0 + 8) * 36 + ca + 4];
                aL[mt][0] = QL[r0 * 36 + ca];       aL[mt][1] = QL[(r0 + 8) * 36 + ca];
                aL[mt][2] = QL[r0 * 36 + ca + 4];   aL[mt][3] = QL[(r0 + 8) * 36 + ca + 4];
            }
#pragma unroll
            for (int nt = 0; nt < 2; nt++) {
                int nc = wnA + nt * 8 + grp;
                bH[nt][0] = KH[(kb + thr) * 72 + nc];
                bH[nt][1] = KH[(kb + thr + 4) * 72 + nc];
                bL[nt][0] = KL[(kb + thr) * 72 + nc];
                bL[nt][1] = KL[(kb + thr + 4) * 72 + nc];
            }
#pragma unroll
            for (int mt = 0; mt < 2; mt++)
#pragma unroll
                for (int nt = 0; nt < 2; nt++) {
                    MMA_TF32(acc[mt][nt], aH[mt][0], aH[mt][1], aH[mt][2], aH[mt][3],
                             bH[nt][0], bH[nt][1]);
                    MMA_TF32(acc[mt][nt], aH[mt][0], aH[mt][1], aH[mt][2], aH[mt][3],
                             bL[nt][0], bL[nt][1]);
                    MMA_TF32(acc[mt][nt], aL[mt][0], aL[mt][1], aL[mt][2], aL[mt][3],
                             bH[nt][0], bH[nt][1]);
                }
        }

        int cbg = c0 << 6;
#pragma unroll
        for (int mt = 0; mt < 2; mt++) {
            int r0 = wmA + mt * 16 + grp, r1 = r0 + 8;
            int q0 = (r0 >> 3) * 23 + (r0 & 7);
            int q1 = (r1 >> 3) * 23 + (r1 & 7);
#pragma unroll
            for (int nt = 0; nt < 2; nt++) {
                int lc = wnA + nt * 8 + 2 * thr;
                int jg0 = cbg + lc, jg1 = jg0 + 1;
                int b0 = (15 - (jg0 >> 4)) * 23 + (15 - (jg0 & 15));
                int b1 = (15 - (jg1 >> 4)) * 23 + (15 - (jg1 & 15));
                float p00 = __expf(acc[mt][nt][0] - bound + bsm[b0 + q0]);
                float p01 = __expf(acc[mt][nt][1] - bound + bsm[b1 + q0]);
                float p10 = __expf(acc[mt][nt][2] - bound + bsm[b0 + q1]);
                float p11 = __expf(acc[mt][nt][3] - bound + bsm[b1 + q1]);
                rs[mt * 2]     += p00 + p01;
                rs[mt * 2 + 1] += p10 + p11;
                float2 w0 = {__uint_as_float(f2tf32(p00)), __uint_as_float(f2tf32(p01))};
                float2 w1 = {__uint_as_float(f2tf32(p10)), __uint_as_float(f2tf32(p11))};
                *(float2*)&Sp[r0 * 68 + lc] = w0;
                *(float2*)&Sp[r1 * 68 + lc] = w1;
            }
        }
        __syncthreads();

        float vvN[8] = {0, 0, 0, 0, 0, 0, 0, 0};
        if (okN) {
            float4 v0 = *(const float4*)(vv + gbN), v1 = *(const float4*)(vv + gbN + 4);
            vvN[0] = v0.x; vvN[1] = v0.y; vvN[2] = v0.z; vvN[3] = v0.w;
            vvN[4] = v1.x; vvN[5] = v1.y; vvN[6] = v1.z; vvN[7] = v1.w;
        }

        const unsigned* SPu = (const unsigned*)Sp;
        const unsigned* VU  = (const unsigned*)(Vs + buf * (64 * 40));
        int ra = mB * 16 + grp;
#pragma unroll
        for (int ks = 0; ks < 8; ks++) {
            int kb = ks * 8;
            unsigned a0 = SPu[ra * 68 + kb + thr];
            unsigned a1 = SPu[(ra + 8) * 68 + kb + thr];
            unsigned a2 = SPu[ra * 68 + kb + thr + 4];
            unsigned a3 = SPu[(ra + 8) * 68 + kb + thr + 4];
#pragma unroll
            for (int nt = 0; nt < 2; nt++) {
                int col = nB * 16 + nt * 8 + grp;
                unsigned b0 = VU[(kb + thr) * 40 + col];
                unsigned b1 = VU[(kb + thr + 4) * 40 + col];
                MMA_TF32(oacc[nt], a0, a1, a2, a3, b0, b1);
            }
        }

        if (have_next) {
            float* KHn = KsH + nbuf * (32 * 72);
            float* KLn = KsL + nbuf * (32 * 72);
            float* Vn  = Vs  + nbuf * (64 * 40);
#pragma unroll
            for (int i = 0; i < 8; i++) {
                unsigned hb, lb;
                split_tf32(kvN[i], hb, lb);
                KHn[(d1 + i) * 72 + jst] = __uint_as_float(hb);
                KLn[(d1 + i) * 72 + jst] = __uint_as_float(lb);
            }
            float vh[8];
#pragma unroll
            for (int i = 0; i < 8; i++) vh[i] = __uint_as_float(f2tf32(vvN[i]));
            *(float4*)&Vn[jst * 40 + d1]     = *(float4*)&vh[0];
            *(float4*)&Vn[jst * 40 + d1 + 4] = *(float4*)&vh[4];
        }
        __syncthreads();
    }

#pragma unroll
    for (int i = 0; i < 4; i++) {
        rs[i] += __shfl_xor_sync(0xffffffffu, rs[i], 1);
        rs[i] += __shfl_xor_sync(0xffffffffu, rs[i], 2);
    }
    if (thr == 0) {
#pragma unroll
        for (int mt = 0; mt < 2; mt++) {
#pragma unroll
            for (int hh = 0; hh < 2; hh++) {
                int row = wmA + mt * 16 + hh * 8 + grp;
                lrd[(warp >> 1) * 64 + row] = rs[mt * 2 + hh];
            }
        }
    }
    __syncthreads();
    if (t < 64)
        lfn[t] = 1.0f / (lrd[t] + lrd[64 + t] + lrd[128 + t] + lrd[192 + t]);
    __syncthreads();

    // normalize + write (tf32-rounded so proj GEMM can copy raw)
    {
        int r0 = mB * 16 + grp, r1 = r0 + 8;
        float inv0 = lfn[r0], inv1 = lfn[r1];
        int py0 = wr * 8 + (r0 >> 3), px0 = wc * 8 + (r0 & 7);
        int py1 = wr * 8 + (r1 >> 3), px1 = wc * 8 + (r1 & 7);
        float* op0 = out + (size_t)(((b << 7) | py0) << 7 | px0) * CH + h * HD;
        float* op1 = out + (size_t)(((b << 7) | py1) << 7 | px1) * CH + h * HD;
#pragma unroll
        for (int nt = 0; nt < 2; nt++) {
            int col = nB * 16 + nt * 8 + 2 * thr;
            float2 w0 = {__uint_as_float(f2tf32(oacc[nt][0] * inv0)),
                         __uint_as_float(f2tf32(oacc[nt][1] * inv0))};
            float2 w1 = {__uint_as_float(f2tf32(oacc[nt][2] * inv1)),
                         __uint_as_float(f2tf32(oacc[nt][3] * inv1))};
            *(float2*)(op0 + col) = w0;
            *(float2*)(op1 + col) = w1;
        }
    }
}

// ---------------- launch ----------------
extern "C" void kernel_launch(void* const* d_in, const int* in_sizes, int n_in,
                              void* d_out, int out_size) {
    const float* x           = (const float*)d_in[0];
    const float* w_qkv       = (const float*)d_in[1];
    const float* w_dw        = (const float*)d_in[2];
    const float* ln_g        = (const float*)d_in[3];
    const float* ln_b        = (const float*)d_in[4];
    const float* q_bias      = (const float*)d_in[5];
    const float* v_bias      = (const float*)d_in[6];
    const float* logit_scale = (const float*)d_in[7];
    const float* cpb_w1      = (const float*)d_in[8];
    const float* cpb_b1      = (const float*)d_in[9];
    const float* cpb_w2      = (const float*)d_in[10];
    const float* w_proj      = (const float*)d_in[11];
    float* out = (float*)d_out;

    float *qkv, *qn, *kn, *vv, *att, *btab, *wq, *wp;
    cudaGetSymbolAddress((void**)&qkv,  g_qkv);
    cudaGetSymbolAddress((void**)&qn,   g_qn);
    cudaGetSymbolAddress((void**)&kn,   g_kn);
    cudaGetSymbolAddress((void**)&vv,   g_v);
    cudaGetSymbolAddress((void**)&att,  g_att);
    cudaGetSymbolAddress((void**)&btab, g_btab);
    cudaGetSymbolAddress((void**)&wq,   g_wq);
    cudaGetSymbolAddress((void**)&wp,   g_wp);

    int smem_attn = A_TOT * 4;
    cudaFuncSetAttribute(attn_kernel, cudaFuncAttributeMaxDynamicSharedMemorySize, smem_attn);
    cudaFuncSetAttribute(mma_gemm, cudaFuncAttributeMaxDynamicSharedMemorySize, GEMM_SMEM);

    cpb_kernel<<<NREL, 256>>>(cpb_w1, cpb_b1, cpb_w2, btab);
    // pre-round GEMM operands to tf32 (x -> att scratch; weights -> scratch)
    round_tf32_kernel<<<(NPIX * CH / 4 + 255) / 256, 256>>>(x, att, NPIX * CH / 4);
    round_tf32_kernel<<<(CH * C3 / 4 + 255) / 256, 256>>>(w_qkv, wq, CH * C3 / 4);
    round_tf32_kernel<<<(CH * CH / 4 + 255) / 256, 256>>>(w_proj, wp, CH * CH / 4);

    mma_gemm<<<dim3(C3 / 128, NPIX / 128), 256, GEMM_SMEM>>>(NPIX, C3, att, wq, qkv);
    conv_ln_kernel<<<NPIX / 4, 192>>>(qkv, w_dw, ln_g, ln_b, q_bias, v_bias, logit_scale,
                                      qn, kn, vv);
    attn_kernel<<<dim3(512, 8), 256, smem_attn>>>(qn, kn, vv, btab, logit_scale, att);
    mma_gemm<<<dim3(CH / 128, NPIX / 128), 256, GEMM_SMEM>>>(NPIX, CH, att, wp, out);
}

// round 16
// speedup vs baseline: 1.2517x; 1.0473x over previous
#include <cuda_runtime.h>
#include <math.h>
#include <stdint.h>

// ---------------- problem constants ----------------
constexpr int BATCH = 2, HH = 128, WW = 128, CH = 256;
constexpr int HEADS = 8, HD = 32;
constexpr int NPIX = BATCH * HH * WW;   // 32768
constexpr int C3 = 3 * CH;              // 768
constexpr int NREL = 23 * 23;           // 529

// ---------------- device scratch (allocation-free) ----------------
__device__ float g_qkv[NPIX * C3];
__device__ float g_qn [NPIX * CH];
__device__ float g_kn [NPIX * CH];
__device__ float g_v  [NPIX * CH];
__device__ float g_att[NPIX * CH];   // tf32-rounded x early, attention output later
__device__ float g_btab[NREL * HEADS];
__device__ float g_wq[CH * C3];      // tf32-rounded w_qkv
__device__ float g_wp[CH * CH];      // tf32-rounded w_proj

// ---------------- tf32 helpers ----------------
__device__ __forceinline__ unsigned f2tf32(float x) {
    unsigned r;
    asm("cvt.rna.tf32.f32 %0, %1;" : "=r"(r) : "f"(x));
    return r;
}
__device__ __forceinline__ void split_tf32(float x, unsigned& hi, unsigned& lo) {
    hi = f2tf32(x);
    lo = f2tf32(x - __uint_as_float(hi));
}
#define MMA_TF32(C, A0, A1, A2, A3, B0, B1)                                    \
    asm volatile(                                                              \
        "mma.sync.aligned.m16n8k8.row.col.f32.tf32.tf32.f32 "                  \
        "{%0,%1,%2,%3}, {%4,%5,%6,%7}, {%8,%9}, {%0,%1,%2,%3};"                \
        : "+f"((C)[0]), "+f"((C)[1]), "+f"((C)[2]), "+f"((C)[3])               \
        : "r"(A0), "r"(A1), "r"(A2), "r"(A3), "r"(B0), "r"(B1))

__device__ __forceinline__ uint32_t smem_u32(const void* p) {
    uint32_t a;
    asm("{ .reg .u64 tmp; cvta.to.shared.u64 tmp, %1; cvt.u32.u64 %0, tmp; }"
        : "=r"(a) : "l"(p));
    return a;
}
__device__ __forceinline__ void cp_async16(uint32_t saddr, const void* gaddr) {
    asm volatile("cp.async.cg.shared.global [%0], [%1], 16;"
                 :: "r"(saddr), "l"(gaddr) : "memory");
}
__device__ __forceinline__ void cp_async16z(uint32_t saddr, const void* gaddr, unsigned sz) {
    asm volatile("cp.async.cg.shared.global [%0], [%1], 16, %2;"
                 :: "r"(saddr), "l"(gaddr), "r"(sz) : "memory");
}
#define CP_COMMIT() asm volatile("cp.async.commit_group;" ::: "memory")
#define CP_WAIT(n)  asm volatile("cp.async.wait_group %0;" :: "n"(n) : "memory")

// ---------------- merged elementwise tf32 rounding pass ----------------
constexpr int RN_X  = NPIX * CH / 4;        // 2097152
constexpr int RN_WQ = CH * C3 / 4;          // 49152
constexpr int RN_WP = CH * CH / 4;          // 16384
constexpr int RN_TOT = RN_X + RN_WQ + RN_WP;

__global__ void round_all_kernel(const float* __restrict__ x,
                                 const float* __restrict__ wq_s,
                                 const float* __restrict__ wp_s,
                                 float* __restrict__ xd,
                                 float* __restrict__ wqd,
                                 float* __restrict__ wpd) {
    int i = blockIdx.x * blockDim.x + threadIdx.x;
    const float4* src;
    float4* dst;
    int j;
    if (i < RN_X) { src = (const float4*)x; dst = (float4*)xd; j = i; }
    else if (i < RN_X + RN_WQ) { src = (const float4*)wq_s; dst = (float4*)wqd; j = i - RN_X; }
    else if (i < RN_TOT) { src = (const float4*)wp_s; dst = (float4*)wpd; j = i - RN_X - RN_WQ; }
    else return;
    float4 v = src[j];
    v.x = __uint_as_float(f2tf32(v.x));
    v.y = __uint_as_float(f2tf32(v.y));
    v.z = __uint_as_float(f2tf32(v.z));
    v.w = __uint_as_float(f2tf32(v.w));
    dst[j] = v;
}

// ---------------- CPB relative-bias MLP ----------------
__device__ __forceinline__ float relcoord(int r) {
    float cs = (float)(r - 11) * (8.0f / 7.0f);
    float a = log1pf(fabsf(cs)) * (1.0f / 2.0794415416798357f);
    return cs > 0.0f ? a : (cs < 0.0f ? -a : 0.0f);
}

__global__ void cpb_kernel(const float* __restrict__ w1, const float* __restrict__ b1,
                           const float* __restrict__ w2, float* __restrict__ btab) {
    int i = blockIdx.x;
    float y0 = relcoord(i / 23), y1 = relcoord(i % 23);
    int t = threadIdx.x;
    float part[HEADS];
#pragma unroll
    for (int hh = 0; hh < HEADS; hh++) part[hh] = 0.0f;
    for (int j = t; j < 512; j += 256) {
        float hv = fmaf(y0, w1[j], fmaf(y1, w1[512 + j], b1[j]));
        hv = fmaxf(hv, 0.0f);
#pragma unroll
        for (int hh = 0; hh < HEADS; hh++) part[hh] = fmaf(hv, w2[j * HEADS + hh], part[hh]);
    }
#pragma unroll
    for (int hh = 0; hh < HEADS; hh++)
#pragma unroll
        for (int o = 16; o; o >>= 1) part[hh] += __shfl_xor_sync(0xffffffffu, part[hh], o);
    __shared__ float sm[HEADS][8];
    int lane = t & 31, wrp = t >> 5;
    if (lane == 0)
        for (int hh = 0; hh < HEADS; hh++) sm[hh][wrp] = part[hh];
    __syncthreads();
    if (t < HEADS) {
        float ssum = 0.0f;
        for (int k = 0; k < 8; k++) ssum += sm[t][k];
        btab[i * HEADS + t] = 16.0f / (1.0f + expf(-ssum));
    }
}

// ---------------- tf32 GEMM: cp.async staging, BK=32, 2 blocks/SM (R15 exact) ----------------
constexpr int GBM = 128, GBN = 128, GBK = 32, GK = 256;
constexpr int AST = GBK + 4;   // 36
constexpr int BST = GBN + 8;   // 136
constexpr int ABUF = GBM * AST;
constexpr int BBUF = GBK * BST;
constexpr int GEMM_SMEM = 2 * (ABUF + BBUF) * 4;

__global__ __launch_bounds__(256, 2) void mma_gemm(int M, int N,
                                                   const float* __restrict__ A,
                                                   const float* __restrict__ B,
                                                   float* __restrict__ C) {
    extern __shared__ float smf[];
    uint32_t sbase = smem_u32(smf);

    int tid = threadIdx.x;
    int warp = tid >> 5, lane = tid & 31;
    int wm = (warp & 1) * 64, wn = (warp >> 1) * 32;
    int brow = blockIdx.y * GBM, bcol = blockIdx.x * GBN;
    int grp = lane >> 2, thr = lane & 3;

    float acc[4][4][4];
#pragma unroll
    for (int i = 0; i < 4; i++)
#pragma unroll
        for (int j = 0; j < 4; j++)
#pragma unroll
            for (int r = 0; r < 4; r++) acc[i][j][r] = 0.0f;

    int aRow = tid >> 1, aCol = (tid & 1) << 4;
    int bRow = tid >> 3, bCol = (tid & 7) << 4;

    const float* Ap = A + (size_t)(brow + aRow) * GK + aCol;
    const float* Bp = B + (size_t)bRow * N + bcol + bCol;
    uint32_t asA = sbase + (uint32_t)(aRow * AST + aCol) * 4;
    uint32_t asB = sbase + (uint32_t)(2 * ABUF + bRow * BST + bCol) * 4;

    constexpr int niter = GK / GBK;   // 8

    {
        const float* ag = Ap;
        cp_async16(asA, ag);      cp_async16(asA + 16, ag + 4);
        cp_async16(asA + 32, ag + 8); cp_async16(asA + 48, ag + 12);
        const float* bg = Bp;
        cp_async16(asB, bg);      cp_async16(asB + 16, bg + 4);
        cp_async16(asB + 32, bg + 8); cp_async16(asB + 48, bg + 12);
        CP_COMMIT();
    }

    for (int iter = 0; iter < niter; iter++) {
        int buf = iter & 1;
        if (iter + 1 < niter) {
            int nb = buf ^ 1;
            uint32_t aA = asA + (uint32_t)(nb * ABUF) * 4;
            uint32_t aB = asB + (uint32_t)(nb * BBUF) * 4;
            const float* ag = Ap + (iter + 1) * GBK;
            cp_async16(aA, ag);       cp_async16(aA + 16, ag + 4);
            cp_async16(aA + 32, ag + 8);  cp_async16(aA + 48, ag + 12);
            const float* bg = Bp + (size_t)(iter + 1) * GBK * N;
            cp_async16(aB, bg);       cp_async16(aB + 16, bg + 4);
            cp_async16(aB + 32, bg + 8);  cp_async16(aB + 48, bg + 12);
            CP_COMMIT();
            CP_WAIT(1);
        } else {
            CP_WAIT(0);
        }
        __syncthreads();

        const unsigned* Acur = (const unsigned*)(smf + buf * ABUF);
        const unsigned* Bcur = (const unsigned*)(smf + 2 * ABUF + buf * BBUF);
#pragma unroll
        for (int kstep = 0; kstep < 4; kstep++) {
            int kb = kstep * 8;
            unsigned a[4][4], bfr[4][2];
#pragma unroll
            for (int mt = 0; mt < 4; mt++) {
                int r0 = wm + mt * 16 + grp;
                int ca = kb + thr;
                a[mt][0] = Acur[r0 * AST + ca];
                a[mt][1] = Acur[(r0 + 8) * AST + ca];
                a[mt][2] = Acur[r0 * AST + ca + 4];
                a[mt][3] = Acur[(r0 + 8) * AST + ca + 4];
            }
#pragma unroll
            for (int nt = 0; nt < 4; nt++) {
                int kr = kb + thr;
                int nc = wn + nt * 8 + grp;
                bfr[nt][0] = Bcur[kr * BST + nc];
                bfr[nt][1] = Bcur[(kr + 4) * BST + nc];
            }
#pragma unroll
            for (int mt = 0; mt < 4; mt++)
#pragma unroll
                for (int nt = 0; nt < 4; nt++)
                    MMA_TF32(acc[mt][nt], a[mt][0], a[mt][1], a[mt][2], a[mt][3],
                             bfr[nt][0], bfr[nt][1]);
        }
        __syncthreads();
    }

#pragma unroll
    for (int mt = 0; mt < 4; mt++) {
#pragma unroll
        for (int nt = 0; nt < 4; nt++) {
            int row = brow + wm + mt * 16 + grp;
            int col = bcol + wn + nt * 8 + thr * 2;
            float2 v0 = {acc[mt][nt][0], acc[mt][nt][1]};
            float2 v1 = {acc[mt][nt][2], acc[mt][nt][3]};
            *(float2*)(C + (size_t)row * N + col) = v0;
            *(float2*)(C + (size_t)(row + 8) * N + col) = v1;
        }
    }
}

// ---------------- conv + LN + biases + l2norm: 4 px/block, 192 threads; vv tf32-rounded ----------------
__global__ __launch_bounds__(192) void conv_ln_kernel(
    const float* __restrict__ qkv, const float* __restrict__ wdw,
    const float* __restrict__ ln_g, const float* __restrict__ ln_b,
    const float* __restrict__ q_bias, const float* __restrict__ v_bias,
    const float* __restrict__ logit_scale,
    float* __restrict__ qn, float* __restrict__ kn, float* __restrict__ vv) {
    int pixbase = blockIdx.x << 2;
    int b = pixbase >> 14, y = (pixbase >> 7) & 127, x0 = pixbase & 127;
    int t = threadIdx.x;
    int c = t << 2;

    float4 wv[9];
#pragma unroll
    for (int i = 0; i < 9; i++) wv[i] = *(const float4*)&wdw[i * C3 + c];

    float4 cv[4];
#pragma unroll
    for (int p = 0; p < 4; p++) cv[p] = make_float4(0.f, 0.f, 0.f, 0.f);

#pragma unroll
    for (int dy = 0; dy < 3; dy++) {
        int yy = y + dy - 1;
        if ((unsigned)yy >= (unsigned)HH) continue;
        float4 rv[6];
#pragma unroll
        for (int dx = 0; dx < 6; dx++) {
            int xx = x0 + dx - 1;
            if ((unsigned)xx < (unsigned)WW)
                rv[dx] = *(const float4*)&qkv[(size_t)(((b << 7) | yy) << 7 | xx) * C3 + c];
            else
                rv[dx] = make_float4(0.f, 0.f, 0.f, 0.f);
        }
#pragma unroll
        for (int p = 0; p < 4; p++) {
#pragma unroll
            for (int kx = 0; kx < 3; kx++) {
                float4 wk = wv[dy * 3 + kx];
                float4 xv = rv[p + kx];
                cv[p].x = fmaf(wk.x, xv.x, cv[p].x);
                cv[p].y = fmaf(wk.y, xv.y, cv[p].y);
                cv[p].z = fmaf(wk.z, xv.z, cv[p].z);
                cv[p].w = fmaf(wk.w, xv.w, cv[p].w);
            }
        }
    }

    float s[4], s2[4];
#pragma unroll
    for (int p = 0; p < 4; p++) {
        s[p]  = cv[p].x + cv[p].y + cv[p].z + cv[p].w;
        s2[p] = cv[p].x * cv[p].x + cv[p].y * cv[p].y + cv[p].z * cv[p].z + cv[p].w * cv[p].w;
    }
#pragma unroll
    for (int o = 16; o; o >>= 1) {
#pragma unroll
        for (int p = 0; p < 4; p++) {
            s[p]  += __shfl_xor_sync(0xffffffffu, s[p], o);
            s2[p] += __shfl_xor_sync(0xffffffffu, s2[p], o);
        }
    }
    __shared__ float ws[6][4], ws2[6][4];
    __shared__ float s_mu[4], s_rstd[4];
    int lane = t & 31, wrp = t >> 5;
    if (lane == 0) {
#pragma unroll
        for (int p = 0; p < 4; p++) { ws[wrp][p] = s[p]; ws2[wrp][p] = s2[p]; }
    }
    __syncthreads();
    if (t < 32) {
        int p = t >> 3, j = t & 7;
        float a1 = (j < 6) ? ws[j][p]  : 0.0f;
        float a2 = (j < 6) ? ws2[j][p] : 0.0f;
#pragma unroll
        for (int o = 4; o; o >>= 1) {
            a1 += __shfl_xor_sync(0xffffffffu, a1, o);
            a2 += __shfl_xor_sync(0xffffffffu, a2, o);
        }
        if (j == 0) {
            float mu = a1 * (1.0f / 768.0f);
            float var = a2 * (1.0f / 768.0f) - mu * mu;
            s_mu[p] = mu;
            s_rstd[p] = rsqrtf(var + 1e-5f);
        }
    }
    __syncthreads();

    float4 g  = *(const float4*)&ln_g[c];
    float4 bb = *(const float4*)&ln_b[c];
    float4 vn[4];
#pragma unroll
    for (int p = 0; p < 4; p++) {
        float mu = s_mu[p], rstd = s_rstd[p];
        vn[p].x = (cv[p].x - mu) * rstd * g.x + bb.x;
        vn[p].y = (cv[p].y - mu) * rstd * g.y + bb.y;
        vn[p].z = (cv[p].z - mu) * rstd * g.z + bb.z;
        vn[p].w = (cv[p].w - mu) * rstd * g.w + bb.w;
    }

    if (t < 64) {
        float4 qb = *(const float4*)&q_bias[c];
        float sc = __expf(fminf(logit_scale[t >> 3], 4.6051701859880914f));
        float ss[4];
#pragma unroll
        for (int p = 0; p < 4; p++) {
            vn[p].x += qb.x; vn[p].y += qb.y; vn[p].z += qb.z; vn[p].w += qb.w;
            ss[p] = vn[p].x * vn[p].x + vn[p].y * vn[p].y +
                    vn[p].z * vn[p].z + vn[p].w * vn[p].w;
        }
#pragma unroll
        for (int o = 4; o; o >>= 1)
#pragma unroll
            for (int p = 0; p < 4; p++) ss[p] += __shfl_xor_sync(0xffffffffu, ss[p], o);
#pragma unroll
        for (int p = 0; p < 4; p++) {
            float rn = rsqrtf(fmaxf(ss[p], 1.55e-5f)) * sc;
            float4 o4 = {vn[p].x * rn, vn[p].y * rn, vn[p].z * rn, vn[p].w * rn};
            *(float4*)&qn[(size_t)(pixbase + p) * CH + c] = o4;
        }
    } else if (t < 128) {
        int cc = c - 256;
        float ss[4];
#pragma unroll
        for (int p = 0; p < 4; p++)
            ss[p] = vn[p].x * vn[p].x + vn[p].y * vn[p].y +
                    vn[p].z * vn[p].z + vn[p].w * vn[p].w;
#pragma unroll
        for (int o = 4; o; o >>= 1)
#pragma unroll
            for (int p = 0; p < 4; p++) ss[p] += __shfl_xor_sync(0xffffffffu, ss[p], o);
#pragma unroll
        for (int p = 0; p < 4; p++) {
            float rn = rsqrtf(fmaxf(ss[p], 1.55e-5f));
            float4 o4 = {vn[p].x * rn, vn[p].y * rn, vn[p].z * rn, vn[p].w * rn};
            *(float4*)&kn[(size_t)(pixbase + p) * CH + cc] = o4;
        }
    } else {
        int cc = c - 512;
        float4 vb = *(const float4*)&v_bias[cc];
#pragma unroll
        for (int p = 0; p < 4; p++) {
            // tf32-rounded store: bit-identical to rounding at attn staging
            float4 o4 = {__uint_as_float(f2tf32(vn[p].x + vb.x)),
                         __uint_as_float(f2tf32(vn[p].y + vb.y)),
                         __uint_as_float(f2tf32(vn[p].z + vb.z)),
                         __uint_as_float(f2tf32(vn[p].w + vb.w))};
            *(float4*)&vv[(size_t)(pixbase + p) * CH + cc] = o4;
        }
    }
}

// ---------------- attention: split-tf32 QK^T, single-tf32 PV, db K/V, cp.async V ----------------
constexpr int A_QSH = 0;
constexpr int A_QSL = A_QSH + 64 * 36;
constexpr int A_KSH = A_QSL + 64 * 36;
constexpr int A_KSL = A_KSH + 2 * 32 * 72;
constexpr int A_VS  = A_KSL + 2 * 32 * 72;
constexpr int A_SP  = A_VS + 2 * 64 * 40;
constexpr int A_BSM = A_SP + 64 * 68;
constexpr int A_LRD = A_BSM + NREL;
constexpr int A_LFN = A_LRD + 256;
constexpr int A_TOT = A_LFN + 64;

__global__ __launch_bounds__(256, 2) void attn_kernel(
    const float* __restrict__ qn, const float* __restrict__ kn,
    const float* __restrict__ vv, const float* __restrict__ btab,
    const float* __restrict__ logit_scale, float* __restrict__ out) {
    extern __shared__ float sm[];
    float* QsH = sm + A_QSH;  float* QsL = sm + A_QSL;
    float* KsH = sm + A_KSH;  float* KsL = sm + A_KSL;
    float* Vs  = sm + A_VS;
    float* Sp  = sm + A_SP;
    float* bsm = sm + A_BSM;
    float* lrd = sm + A_LRD;
    float* lfn = sm + A_LFN;

    int w = blockIdx.x, h = blockIdx.y;
    int b = w >> 8, wr = (w >> 4) & 15, wc = w & 15;
    int t = threadIdx.x;
    int warp = t >> 5, lane = t & 31, grp = lane >> 2, thr = lane & 3;
    float bound = __expf(fminf(logit_scale[h], 4.6051701859880914f)) + 16.0f;

    for (int i = t; i < NREL; i += 256) bsm[i] = btab[i * HEADS + h];

    {
        int row = t & 63, d0 = (t >> 6) << 3;
        int py = wr * 8 + (row >> 3), px = wc * 8 + (row & 7);
        const float* qp = qn + (size_t)(((b << 7) | py) << 7 | px) * CH + h * HD + d0;
        float4 a = *(const float4*)qp;
        float4 bq = *(const float4*)(qp + 4);
        float v[8] = {a.x, a.y, a.z, a.w, bq.x, bq.y, bq.z, bq.w};
#pragma unroll
        for (int i = 0; i < 8; i++) {
            unsigned hb, lb;
            split_tf32(v[i], hb, lb);
            QsH[row * 36 + d0 + i] = __uint_as_float(hb);
            QsL[row * 36 + d0 + i] = __uint_as_float(lb);
        }
    }

    int jst = t & 63, d1 = (t >> 6) << 3;
    uint32_t vdst0 = smem_u32(&Vs[jst * 40 + d1]);

    // prologue: V chunk 0 via cp.async (vv pre-rounded); K chunk 0 split-staged
    {
        int gy = wr * 8 - 4 + (jst >> 4), gx = wc * 8 - 4 + (jst & 15);
        bool ok = (unsigned)gy < 128u && (unsigned)gx < 128u;
        size_t gb = ok ? (size_t)(((b << 7) | gy) << 7 | gx) * CH + h * HD + d1 : 0;
        unsigned sz = ok ? 16u : 0u;
        const float* vsrc = ok ? (vv + gb) : vv;
        cp_async16z(vdst0, vsrc, sz);
        cp_async16z(vdst0 + 16, vsrc + 4, sz);
        CP_COMMIT();
        float kv[8] = {0, 0, 0, 0, 0, 0, 0, 0};
        if (ok) {
            float4 k0 = *(const float4*)(kn + gb), k1 = *(const float4*)(kn + gb + 4);
            kv[0] = k0.x; kv[1] = k0.y; kv[2] = k0.z; kv[3] = k0.w;
            kv[4] = k1.x; kv[5] = k1.y; kv[6] = k1.z; kv[7] = k1.w;
        }
#pragma unroll
        for (int i = 0; i < 8; i++) {
            unsigned hb, lb;
            split_tf32(kv[i], hb, lb);
            KsH[(d1 + i) * 72 + jst] = __uint_as_float(hb);
            KsL[(d1 + i) * 72 + jst] = __uint_as_float(lb);
        }
        CP_WAIT(0);
    }
    __syncthreads();

    int wmA = (warp & 1) * 32, wnA = (warp >> 1) * 16;
    int mB = warp & 3, nB = warp >> 2;

    float oacc[2][4];
#pragma unroll
    for (int nt = 0; nt < 2; nt++)
#pragma unroll
        for (int r = 0; r < 4; r++) oacc[nt][r] = 0.0f;
    float rs[4] = {0.0f, 0.0f, 0.0f, 0.0f};

    for (int c0 = 0; c0 < 4; c0++) {
        int buf = c0 & 1, nbuf = buf ^ 1;
        bool have_next = (c0 < 3);

        size_t gbN = 0;
        bool okN = false;
        if (have_next) {
            int jgN = ((c0 + 1) << 6) + jst;
            int gy = wr * 8 - 4 + (jgN >> 4), gx = wc * 8 - 4 + (jgN & 15);
            okN = (unsigned)gy < 128u && (unsigned)gx < 128u;
            if (okN) gbN = (size_t)(((b << 7) | gy) << 7 | gx) * CH + h * HD + d1;
            // issue next V copy immediately — overlaps QK^T + softmax + PV
            unsigned sz = okN ? 16u : 0u;
            const float* vsrc = okN ? (vv + gbN) : vv;
            uint32_t vdst = vdst0 + (uint32_t)(nbuf * (64 * 40)) * 4;
            cp_async16z(vdst, vsrc, sz);
            cp_async16z(vdst + 16, vsrc + 4, sz);
            CP_COMMIT();
        }

        float kvN[8] = {0, 0, 0, 0, 0, 0, 0, 0};
        if (okN) {
            float4 k0 = *(const float4*)(kn + gbN), k1 = *(const float4*)(kn + gbN + 4);
            kvN[0] = k0.x; kvN[1] = k0.y; kvN[2] = k0.z; kvN[3] = k0.w;
            kvN[4] = k1.x; kvN[5] = k1.y; kvN[6] = k1.z; kvN[7] = k1.w;
        }

        const unsigned* QH = (const unsigned*)QsH;
        const unsigned* QL = (const unsigned*)QsL;
        const unsigned* KH = (const unsigned*)(KsH + buf * (32 * 72));
        const unsigned* KL = (const unsigned*)(KsL + buf * (32 * 72));
        float acc[2][2][4];
#pragma unroll
        for (int mt = 0; mt < 2; mt++)
#pragma unroll
            for (int nt = 0; nt < 2; nt++)
#pragma unroll
                for (int r = 0; r < 4; r++) acc[mt][nt][r] = 0.0f;
#pragma unroll
        for (int ks = 0; ks < 4; ks++) {
            int kb = ks * 8;
            unsigned aH[2][4], aL[2][4], bH[2][2], bL[2][2];
#pragma unroll
            for (int mt = 0; mt < 2; mt++) {
                int r0 = wmA + mt * 16 + grp;
                int ca = kb + thr;
                aH[mt][0] = QH[r0 * 36 + ca];       aH[mt][1] = QH[(r0 + 8) * 36 + ca];
                aH[mt][2] = QH[r0 * 36 + ca + 4];   aH[mt][3] = QH[(r0 + 8) * 36 + ca + 4];
                aL[mt][0] = QL[r0 * 36 + ca];       aL[mt][1] = QL[(r0 + 8) * 36 + ca];
                aL[mt][2] = QL[r0 * 36 + ca + 4];   aL[mt][3] = QL[(r0 + 8) * 36 + ca + 4];
            }
#pragma unroll
            for (int nt = 0; nt < 2; nt++) {
                int nc = wnA + nt * 8 + grp;
                bH[nt][0] = KH[(kb + thr) * 72 + nc];
                bH[nt][1] = KH[(kb + thr + 4) * 72 + nc];
                bL[nt][0] = KL[(kb + thr) * 72 + nc];
                bL[nt][1] = KL[(kb + thr + 4) * 72 + nc];
            }
#pragma unroll
            for (int mt = 0; mt < 2; mt++)
#pragma unroll
                for (int nt = 0; nt < 2; nt++) {
                    MMA_TF32(acc[mt][nt], aH[mt][0], aH[mt][1], aH[mt][2], aH[mt][3],
                             bH[nt][0], bH[nt][1]);
                    MMA_TF32(acc[mt][nt], aH[mt][0], aH[mt][1], aH[mt][2], aH[mt][3],
                             bL[nt][0], bL[nt][1]);
                    MMA_TF32(acc[mt][nt], aL[mt][0], aL[mt][1], aL[mt][2], aL[mt][3],
                             bH[nt][0], bH[nt][1]);
                }
        }

        int cbg = c0 << 6;
#pragma unroll
        for (int mt = 0; mt < 2; mt++) {
            int r0 = wmA + mt * 16 + grp, r1 = r0 + 8;
            int q0 = (r0 >> 3) * 23 + (r0 & 7);
            int q1 = (r1 >> 3) * 23 + (r1 & 7);
#pragma unroll
            for (int nt = 0; nt < 2; nt++) {
                int lc = wnA + nt * 8 + 2 * thr;
                int jg0 = cbg + lc, jg1 = jg0 + 1;
                int b0 = (15 - (jg0 >> 4)) * 23 + (15 - (jg0 & 15));
                int b1 = (15 - (jg1 >> 4)) * 23 + (15 - (jg1 & 15));
                float p00 = __expf(acc[mt][nt][0] - bound + bsm[b0 + q0]);
                float p01 = __expf(acc[mt][nt][1] - bound + bsm[b1 + q0]);
                float p10 = __expf(acc[mt][nt][2] - bound + bsm[b0 + q1]);
                float p11 = __expf(acc[mt][nt][3] - bound + bsm[b1 + q1]);
                rs[mt * 2]     += p00 + p01;
                rs[mt * 2 + 1] += p10 + p11;
                float2 w0 = {__uint_as_float(f2tf32(p00)), __uint_as_float(f2tf32(p01))};
                float2 w1 = {__uint_as_float(f2tf32(p10)), __uint_as_float(f2tf32(p11))};
                *(float2*)&Sp[r0 * 68 + lc] = w0;
                *(float2*)&Sp[r1 * 68 + lc] = w1;
            }
        }
        __syncthreads();

        const unsigned* SPu = (const unsigned*)Sp;
        const unsigned* VU  = (const unsigned*)(Vs + buf * (64 * 40));
        int ra = mB * 16 + grp;
#pragma unroll
        for (int ks = 0; ks < 8; ks++) {
            int kb = ks * 8;
            unsigned a0 = SPu[ra * 68 + kb + thr];
            unsigned a1 = SPu[(ra + 8) * 68 + kb + thr];
            unsigned a2 = SPu[ra * 68 + kb + thr + 4];
            unsigned a3 = SPu[(ra + 8) * 68 + kb + thr + 4];
#pragma unroll
            for (int nt = 0; nt < 2; nt++) {
                int col = nB * 16 + nt * 8 + grp;
                unsigned b0 = VU[(kb + thr) * 40 + col];
                unsigned b1 = VU[(kb + thr + 4) * 40 + col];
                MMA_TF32(oacc[nt], a0, a1, a2, a3, b0, b1);
            }
        }

        if (have_next) {
            float* KHn = KsH + nbuf * (32 * 72);
            float* KLn = KsL + nbuf * (32 * 72);
#pragma unroll
            for (int i = 0; i < 8; i++) {
                unsigned hb, lb;
                split_tf32(kvN[i], hb, lb);
                KHn[(d1 + i) * 72 + jst] = __uint_as_float(hb);
                KLn[(d1 + i) * 72 + jst] = __uint_as_float(lb);
            }
        }
        CP_WAIT(0);
        __syncthreads();
    }

#pragma unroll
    for (int i = 0; i < 4; i++) {
        rs[i] += __shfl_xor_sync(0xffffffffu, rs[i], 1);
        rs[i] += __shfl_xor_sync(0xffffffffu, rs[i], 2);
    }
    if (thr == 0) {
#pragma unroll
        for (int mt = 0; mt < 2; mt++) {
#pragma unroll
            for (int hh = 0; hh < 2; hh++) {
                int row = wmA + mt * 16 + hh * 8 + grp;
                lrd[(warp >> 1) * 64 + row] = rs[mt * 2 + hh];
            }
        }
    }
    __syncthreads();
    if (t < 64)
        lfn[t] = 1.0f / (lrd[t] + lrd[64 + t] + lrd[128 + t] + lrd[192 + t]);
    __syncthreads();

    {
        int r0 = mB * 16 + grp, r1 = r0 + 8;
        float inv0 = lfn[r0], inv1 = lfn[r1];
        int py0 = wr * 8 + (r0 >> 3), px0 = wc * 8 + (r0 & 7);
        int py1 = wr * 8 + (r1 >> 3), px1 = wc * 8 + (r1 & 7);
        float* op0 = out + (size_t)(((b << 7) | py0) << 7 | px0) * CH + h * HD;
        float* op1 = out + (size_t)(((b << 7) | py1) << 7 | px1) * CH + h * HD;
#pragma unroll
        for (int nt = 0; nt < 2; nt++) {
            int col = nB * 16 + nt * 8 + 2 * thr;
            float2 w0 = {__uint_as_float(f2tf32(oacc[nt][0] * inv0)),
                         __uint_as_float(f2tf32(oacc[nt][1] * inv0))};
            float2 w1 = {__uint_as_float(f2tf32(oacc[nt][2] * inv1)),
                         __uint_as_float(f2tf32(oacc[nt][3] * inv1))};
            *(float2*)(op0 + col) = w0;
            *(float2*)(op1 + col) = w1;
        }
    }
}

// ---------------- launch ----------------
extern "C" void kernel_launch(void* const* d_in, const int* in_sizes, int n_in,
                              void* d_out, int out_size) {
    const float* x           = (const float*)d_in[0];
    const float* w_qkv       = (const float*)d_in[1];
    const float* w_dw        = (const float*)d_in[2];
    const float* ln_g        = (const float*)d_in[3];
    const float* ln_b        = (const float*)d_in[4];
    const float* q_bias      = (const float*)d_in[5];
    const float* v_bias      = (const float*)d_in[6];
    const float* logit_scale = (const float*)d_in[7];
    const float* cpb_w1      = (const float*)d_in[8];
    const float* cpb_b1      = (const float*)d_in[9];
    const float* cpb_w2      = (const float*)d_in[10];
    const float* w_proj      = (const float*)d_in[11];
    float* out = (float*)d_out;

    float *qkv, *qn, *kn, *vv, *att, *btab, *wq, *wp;
    cudaGetSymbolAddress((void**)&qkv,  g_qkv);
    cudaGetSymbolAddress((void**)&qn,   g_qn);
    cudaGetSymbolAddress((void**)&kn,   g_kn);
    cudaGetSymbolAddress((void**)&vv,   g_v);
    cudaGetSymbolAddress((void**)&att,  g_att);
    cudaGetSymbolAddress((void**)&btab, g_btab);
    cudaGetSymbolAddress((void**)&wq,   g_wq);
    cudaGetSymbolAddress((void**)&wp,   g_wp);

    int smem_attn = A_TOT * 4;
    cudaFuncSetAttribute(attn_kernel, cudaFuncAttributeMaxDynamicSharedMemorySize, smem_attn);
    cudaFuncSetAttribute(mma_gemm, cudaFuncAttributeMaxDynamicSharedMemorySize, GEMM_SMEM);

    cpb_kernel<<<NREL, 256>>>(cpb_w1, cpb_b1, cpb_w2, btab);
    round_all_kernel<<<(RN_TOT + 255) / 256, 256>>>(x, w_qkv, w_proj, att, wq, wp);

    mma_gemm<<<dim3(C3 / 128, NPIX / 128), 256, GEMM_SMEM>>>(NPIX, C3, att, wq, qkv);
    conv_ln_kernel<<<NPIX / 4, 192>>>(qkv, w_dw, ln_g, ln_b, q_bias, v_bias, logit_scale,
                                      qn, kn, vv);
    attn_kernel<<<dim3(512, 8), 256, smem_attn>>>(qn, kn, vv, btab, logit_scale, att);
    mma_gemm<<<dim3(CH / 128, NPIX / 128), 256, GEMM_SMEM>>>(NPIX, CH, att, wp, out);
}